// round 5
// baseline (speedup 1.0000x reference)
#include <cuda_runtime.h>
#include <cuda_bf16.h>
#include <cstdint>

#define B_   2
#define S_   2048
#define E_   1024
#define H_   16
#define DH_  64
#define FF_  4096
#define TOK  (B_*S_)   // 4096
#define NQKV 3072

// ---------------- scratch (no allocs allowed) ----------------
__device__ __nv_bfloat16 g_nx_hi [TOK*(size_t)E_],  g_nx_lo [TOK*(size_t)E_];
__device__ __nv_bfloat16 g_wqkv_hi[(size_t)NQKV*E_], g_wqkv_lo[(size_t)NQKV*E_];
__device__ __nv_bfloat16 g_wo_hi [(size_t)E_*E_],   g_wo_lo [(size_t)E_*E_];
__device__ __nv_bfloat16 g_w1_hi [(size_t)FF_*E_],  g_w1_lo [(size_t)FF_*E_];
__device__ __nv_bfloat16 g_w2_hi [(size_t)E_*FF_],  g_w2_lo [(size_t)E_*FF_];
__device__ float g_q[(size_t)B_*H_*S_*DH_];
__device__ float g_k[(size_t)B_*H_*S_*DH_];
__device__ float g_v[(size_t)B_*H_*S_*DH_];
__device__ __nv_bfloat16 g_attn_hi[TOK*(size_t)E_], g_attn_lo[TOK*(size_t)E_];
__device__ float g_x1[TOK*(size_t)E_];
__device__ __nv_bfloat16 g_nx2_hi[TOK*(size_t)E_],  g_nx2_lo[TOK*(size_t)E_];
__device__ __nv_bfloat16 g_ffn_hi[TOK*(size_t)FF_], g_ffn_lo[TOK*(size_t)FF_];

__device__ __forceinline__ float neg_inf() { return __int_as_float(0xff800000u); }

// ---------------- PTX helpers (all base-sm_80/90 features, no arch-specific) --
__device__ __forceinline__ uint32_t smem_u32(const void* p) {
    uint32_t a;
    asm("{ .reg .u64 t; cvta.to.shared.u64 t, %1; cvt.u32.u64 %0, t; }" : "=r"(a) : "l"(p));
    return a;
}
__device__ __forceinline__ void cp16(uint32_t s, const void* g) {
    asm volatile("cp.async.cg.shared.global [%0], [%1], 16;" :: "r"(s), "l"(g));
}
#define CP_COMMIT() asm volatile("cp.async.commit_group;" ::: "memory")
#define CP_WAIT(n)  asm volatile("cp.async.wait_group %0;" :: "n"(n) : "memory")

__device__ __forceinline__ void ldm_x4(uint32_t& r0, uint32_t& r1, uint32_t& r2,
                                       uint32_t& r3, uint32_t a) {
    asm volatile("ldmatrix.sync.aligned.m8n8.x4.shared.b16 {%0,%1,%2,%3}, [%4];"
                 : "=r"(r0), "=r"(r1), "=r"(r2), "=r"(r3) : "r"(a));
}
__device__ __forceinline__ void mma16816(float* c, uint32_t a0, uint32_t a1,
                                         uint32_t a2, uint32_t a3,
                                         uint32_t b0, uint32_t b1) {
    asm volatile(
        "mma.sync.aligned.m16n8k16.row.col.f32.bf16.bf16.f32 "
        "{%0,%1,%2,%3},{%4,%5,%6,%7},{%8,%9},{%0,%1,%2,%3};"
        : "+f"(c[0]), "+f"(c[1]), "+f"(c[2]), "+f"(c[3])
        : "r"(a0), "r"(a1), "r"(a2), "r"(a3), "r"(b0), "r"(b1));
}

// ---------------- LayerNorm + bf16 split: one block per token ----------------
__global__ void __launch_bounds__(256) ln_split_kernel(
    const float* __restrict__ x, const float* __restrict__ g,
    const float* __restrict__ bta,
    __nv_bfloat16* __restrict__ ohi, __nv_bfloat16* __restrict__ olo)
{
    __shared__ float sh1[8], sh2[8];
    int tok = blockIdx.x;
    int t = threadIdx.x;
    const float4* xr = (const float4*)(x + (size_t)tok * E_);
    float4 v = xr[t];
    float sum = v.x + v.y + v.z + v.w;
    float sq  = v.x*v.x + v.y*v.y + v.z*v.z + v.w*v.w;
    #pragma unroll
    for (int o = 16; o > 0; o >>= 1) {
        sum += __shfl_xor_sync(0xffffffffu, sum, o);
        sq  += __shfl_xor_sync(0xffffffffu, sq,  o);
    }
    if ((t & 31) == 0) { sh1[t >> 5] = sum; sh2[t >> 5] = sq; }
    __syncthreads();
    if (t < 32) {
        sum = (t < 8) ? sh1[t] : 0.f;
        sq  = (t < 8) ? sh2[t] : 0.f;
        #pragma unroll
        for (int o = 4; o > 0; o >>= 1) {
            sum += __shfl_xor_sync(0xffffffffu, sum, o);
            sq  += __shfl_xor_sync(0xffffffffu, sq,  o);
        }
        if (t == 0) { sh1[0] = sum; sh2[0] = sq; }
    }
    __syncthreads();
    sum = sh1[0]; sq = sh2[0];
    float mu  = sum * (1.0f / E_);
    float var = sq * (1.0f / E_) - mu * mu;
    float rs  = rsqrtf(var + 1e-5f);
    float4 gv = ((const float4*)g)[t];
    float4 bv = ((const float4*)bta)[t];
    float o4[4];
    o4[0] = (v.x - mu) * rs * gv.x + bv.x;
    o4[1] = (v.y - mu) * rs * gv.y + bv.y;
    o4[2] = (v.z - mu) * rs * gv.z + bv.z;
    o4[3] = (v.w - mu) * rs * gv.w + bv.w;
    size_t base = (size_t)tok * E_ + t * 4;
    __nv_bfloat16 h[4], l[4];
    #pragma unroll
    for (int i = 0; i < 4; i++) {
        h[i] = __float2bfloat16(o4[i]);
        l[i] = __float2bfloat16(o4[i] - __bfloat162float(h[i]));
    }
    *(__nv_bfloat162*)(ohi + base)     = __halves2bfloat162(h[0], h[1]);
    *(__nv_bfloat162*)(ohi + base + 2) = __halves2bfloat162(h[2], h[3]);
    *(__nv_bfloat162*)(olo + base)     = __halves2bfloat162(l[0], l[1]);
    *(__nv_bfloat162*)(olo + base + 2) = __halves2bfloat162(l[2], l[3]);
}

// ---------------- weight transpose + split: W[K,N] -> Wt[N,K] hi/lo ----------
__global__ void __launch_bounds__(256) wt_split_kernel(
    const float* __restrict__ W, int K, int N,
    __nv_bfloat16* __restrict__ ohi, __nv_bfloat16* __restrict__ olo)
{
    __shared__ float t[32][33];
    int k0 = blockIdx.x * 32, n0 = blockIdx.y * 32;
    int tx = threadIdx.x & 31, ty = threadIdx.x >> 5;
    #pragma unroll
    for (int r = 0; r < 4; r++)
        t[ty + 8*r][tx] = W[(size_t)(k0 + ty + 8*r) * N + n0 + tx];
    __syncthreads();
    #pragma unroll
    for (int r = 0; r < 4; r++) {
        float v = t[tx][ty + 8*r];
        __nv_bfloat16 h = __float2bfloat16(v);
        __nv_bfloat16 l = __float2bfloat16(v - __bfloat162float(h));
        size_t o = (size_t)(n0 + ty + 8*r) * K + k0 + tx;
        ohi[o] = h; olo[o] = l;
    }
}

// QKV weights [H,E,DH] x3 -> fused Wt[3072, E] hi/lo (row n: mat=n>>10,h,d)
__global__ void __launch_bounds__(256) wqkv_split_kernel(
    const float* __restrict__ Wq, const float* __restrict__ Wk,
    const float* __restrict__ Wv,
    __nv_bfloat16* __restrict__ ohi, __nv_bfloat16* __restrict__ olo)
{
    __shared__ float t[32][33];
    int e0 = blockIdx.x * 32, n0 = blockIdx.y * 32;
    const float* Wm = (n0 < 1024) ? Wq : (n0 < 2048) ? Wk : Wv;
    int nn = n0 & 1023;
    int h = nn >> 6, d0 = nn & 63;
    int tx = threadIdx.x & 31, ty = threadIdx.x >> 5;
    #pragma unroll
    for (int r = 0; r < 4; r++)
        t[ty + 8*r][tx] = Wm[((size_t)h * E_ + e0 + ty + 8*r) * DH_ + d0 + tx];
    __syncthreads();
    #pragma unroll
    for (int r = 0; r < 4; r++) {
        float v = t[tx][ty + 8*r];
        __nv_bfloat16 hh = __float2bfloat16(v);
        __nv_bfloat16 ll = __float2bfloat16(v - __bfloat162float(hh));
        size_t o = (size_t)(n0 + ty + 8*r) * E_ + e0 + tx;
        ohi[o] = hh; olo[o] = ll;
    }
}

// ---------------- HMMA GEMM: C[M,N] = A[M,K]*Bt[N,K]^T, 3-term bf16 split ------
// Virtual K = 3K via slabs: (Ahi,Bhi), (Alo,Bhi), (Ahi,Blo)
// MODE 0: QKV scatter to q/k/v [B,H,S,DH]
// MODE 1/3: + bias + res -> o0 fp32
// MODE 2: relu(+bias) -> oh/ol bf16 split
#define BK     32
#define LDS    40
#define AELEMS (128 * LDS)             // 5120 bf16
#define ABYTES (AELEMS * 2)            // 10240
#define STG_BYTES (2 * ABYTES)         // A + B per stage
#define GEMM_SMEM (4 * STG_BYTES)      // 81920

template<int MODE>
__global__ void __launch_bounds__(256, 1) gemm_mma_kernel(
    const __nv_bfloat16* __restrict__ Ahi, const __nv_bfloat16* __restrict__ Alo,
    const __nv_bfloat16* __restrict__ Bhi, const __nv_bfloat16* __restrict__ Blo,
    const float* __restrict__ bias, const float* __restrict__ res,
    float* __restrict__ o0, float* __restrict__ o1, float* __restrict__ o2,
    __nv_bfloat16* __restrict__ oh, __nv_bfloat16* __restrict__ ol,
    int K, int ldC)
{
    extern __shared__ __nv_bfloat16 smbuf[];
    const uint32_t sbase = smem_u32(smbuf);
    const int NIT = 3 * K / BK;
    const int t = threadIdx.x;
    const int wid = t >> 5, lane = t & 31;
    const int bm = blockIdx.y * 128, bn = blockIdx.x * 128;
    const int wm = (wid & 1) * 64, wn = (wid >> 1) * 32;

    // slab-mapped source pointers for virtual-K chunk i
    auto aptr = [&](int i) -> const __nv_bfloat16* {
        int kc = i * BK;
        const __nv_bfloat16* s = (kc >= K && kc < 2*K) ? Alo : Ahi;
        return s + (size_t)bm * K + (kc & (K - 1));
    };
    auto bptr = [&](int i) -> const __nv_bfloat16* {
        int kc = i * BK;
        const __nv_bfloat16* s = (kc >= 2*K) ? Blo : Bhi;
        return s + (size_t)bn * K + (kc & (K - 1));
    };
    auto load_stage = [&](int st, const __nv_bfloat16* Ap, const __nv_bfloat16* Bp) {
        uint32_t sa = sbase + st * STG_BYTES;
        #pragma unroll
        for (int p = 0; p < 2; p++) {
            int idx = t + p * 256;
            int row = idx >> 2, ch = idx & 3;
            uint32_t off = (uint32_t)(row * LDS + ch * 8) * 2;
            cp16(sa + off,          Ap + (size_t)row * K + ch * 8);
            cp16(sa + ABYTES + off, Bp + (size_t)row * K + ch * 8);
        }
    };

    // prologue: 3 stages in flight
    #pragma unroll
    for (int s = 0; s < 3; s++) { load_stage(s, aptr(s), bptr(s)); CP_COMMIT(); }

    float c[4][4][4];
    #pragma unroll
    for (int mt = 0; mt < 4; mt++)
        #pragma unroll
        for (int nt = 0; nt < 4; nt++)
            #pragma unroll
            for (int e = 0; e < 4; e++) c[mt][nt][e] = 0.f;

    for (int i = 0; i < NIT; i++) {
        CP_WAIT(2);
        __syncthreads();
        if (i + 3 < NIT) load_stage((i + 3) & 3, aptr(i + 3), bptr(i + 3));
        CP_COMMIT();

        uint32_t sa = sbase + (i & 3) * STG_BYTES;
        uint32_t sb = sa + ABYTES;
        #pragma unroll
        for (int ks = 0; ks < 2; ks++) {
            uint32_t a[4][4];
            #pragma unroll
            for (int mt = 0; mt < 4; mt++) {
                uint32_t addr = sa + (uint32_t)(((wm + mt*16 + (lane & 15)) * LDS
                                  + ks*16 + (lane >> 4) * 8) * 2);
                ldm_x4(a[mt][0], a[mt][1], a[mt][2], a[mt][3], addr);
            }
            uint32_t b[4][2];
            #pragma unroll
            for (int np = 0; np < 2; np++) {
                int nrow = wn + np*16 + (lane & 7) + ((lane >> 4) << 3);
                int ncol = ks*16 + (((lane >> 3) & 1) << 3);
                uint32_t addr = sb + (uint32_t)((nrow * LDS + ncol) * 2);
                uint32_t r0, r1, r2, r3;
                ldm_x4(r0, r1, r2, r3, addr);
                b[2*np][0] = r0; b[2*np][1] = r1;
                b[2*np+1][0] = r2; b[2*np+1][1] = r3;
            }
            #pragma unroll
            for (int mt = 0; mt < 4; mt++)
                #pragma unroll
                for (int nt = 0; nt < 4; nt++)
                    mma16816(c[mt][nt], a[mt][0], a[mt][1], a[mt][2], a[mt][3],
                             b[nt][0], b[nt][1]);
        }
    }

    // ---------------- epilogue ----------------
    const int r = lane >> 2, cq = (lane & 3) * 2;
    #pragma unroll
    for (int mt = 0; mt < 4; mt++) {
        #pragma unroll
        for (int half = 0; half < 2; half++) {
            int m = bm + wm + mt * 16 + r + half * 8;
            #pragma unroll
            for (int nt = 0; nt < 4; nt++) {
                int n = bn + wn + nt * 8 + cq;
                float v0 = c[mt][nt][half * 2 + 0];
                float v1 = c[mt][nt][half * 2 + 1];
                if (MODE == 0) {
                    int mat = n >> 10;
                    float* qkv = (mat == 0) ? o0 : (mat == 1) ? o1 : o2;
                    int hh = (n & 1023) >> 6, d = n & 63;
                    int bb = m >> 11, srow = m & (S_ - 1);
                    float* p = qkv + (((size_t)(bb * H_ + hh) * S_ + srow) << 6) + d;
                    *(float2*)p = make_float2(v0, v1);
                } else if (MODE == 2) {
                    float2 bv = *(const float2*)(bias + n);
                    v0 = fmaxf(v0 + bv.x, 0.f);
                    v1 = fmaxf(v1 + bv.y, 0.f);
                    __nv_bfloat16 h0 = __float2bfloat16(v0);
                    __nv_bfloat16 h1 = __float2bfloat16(v1);
                    __nv_bfloat16 l0 = __float2bfloat16(v0 - __bfloat162float(h0));
                    __nv_bfloat16 l1 = __float2bfloat16(v1 - __bfloat162float(h1));
                    size_t base = (size_t)m * ldC + n;
                    *(__nv_bfloat162*)(oh + base) = __halves2bfloat162(h0, h1);
                    *(__nv_bfloat162*)(ol + base) = __halves2bfloat162(l0, l1);
                } else {
                    size_t base = (size_t)m * ldC + n;
                    float2 bv = *(const float2*)(bias + n);
                    float2 rv = *(const float2*)(res + base);
                    *(float2*)(o0 + base) = make_float2(v0 + bv.x + rv.x,
                                                        v1 + bv.y + rv.y);
                }
            }
        }
    }
}

// ---------------- flash attention (causal), 64x64 tiles, bf16-split output ----
__global__ void __launch_bounds__(256) flash_kernel(
    const float* __restrict__ Q, const float* __restrict__ Kp,
    const float* __restrict__ Vp,
    __nv_bfloat16* __restrict__ Ohi, __nv_bfloat16* __restrict__ Olo)
{
    extern __shared__ float sm[];
    float* Qs = sm;             // [64][64]
    float* Ks = sm + 4096;      // [kk][j] stride 65
    float* Vs = Ks + 4160;      // [key][dim] stride 64
    float* Ps = Vs + 4096;      // [i][k] stride 64

    int qt = blockIdx.x, h = blockIdx.y, b = blockIdx.z;
    int t = threadIdx.x, tx = t & 15, ty = t >> 4;
    int i0 = ty * 4, j0 = tx * 4;

    const float* Qg = Q  + (((size_t)(b * H_ + h)) * S_ + qt * 64) * DH_;
    const float* Kg = Kp + ((size_t)(b * H_ + h)) * S_ * DH_;
    const float* Vg = Vp + ((size_t)(b * H_ + h)) * S_ * DH_;

    for (int i = t; i < 1024; i += 256)
        ((float4*)Qs)[i] = ((const float4*)Qg)[i];

    float mrow[4], lrow[4], o[4][4];
    #pragma unroll
    for (int i = 0; i < 4; i++) {
        mrow[i] = neg_inf(); lrow[i] = 0.f;
        #pragma unroll
        for (int j = 0; j < 4; j++) o[i][j] = 0.f;
    }

    for (int kt = 0; kt <= qt; kt++) {
        __syncthreads();
        const float* kg = Kg + (size_t)kt * 64 * DH_;
        for (int idx = t; idx < 4096; idx += 256)
            Ks[(idx & 63) * 65 + (idx >> 6)] = kg[idx];
        const float* vg = Vg + (size_t)kt * 64 * DH_;
        for (int i = t; i < 1024; i += 256)
            ((float4*)Vs)[i] = ((const float4*)vg)[i];
        __syncthreads();

        float s[4][4];
        #pragma unroll
        for (int i = 0; i < 4; i++)
            #pragma unroll
            for (int j = 0; j < 4; j++) s[i][j] = 0.f;

        for (int kk = 0; kk < 64; kk++) {
            float qr[4], kr[4];
            #pragma unroll
            for (int i = 0; i < 4; i++) qr[i] = Qs[(i0 + i) * 64 + kk];
            #pragma unroll
            for (int j = 0; j < 4; j++) kr[j] = Ks[kk * 65 + j0 + j];
            #pragma unroll
            for (int i = 0; i < 4; i++)
                #pragma unroll
                for (int j = 0; j < 4; j++)
                    s[i][j] = fmaf(qr[i], kr[j], s[i][j]);
        }
        #pragma unroll
        for (int i = 0; i < 4; i++)
            #pragma unroll
            for (int j = 0; j < 4; j++) s[i][j] *= 0.125f;

        if (kt == qt) {
            #pragma unroll
            for (int i = 0; i < 4; i++)
                #pragma unroll
                for (int j = 0; j < 4; j++)
                    if (j0 + j > i0 + i) s[i][j] = neg_inf();
        }

        #pragma unroll
        for (int i = 0; i < 4; i++) {
            float mx = fmaxf(fmaxf(s[i][0], s[i][1]), fmaxf(s[i][2], s[i][3]));
            #pragma unroll
            for (int off = 8; off; off >>= 1)
                mx = fmaxf(mx, __shfl_xor_sync(0xffffffffu, mx, off));
            float mn = fmaxf(mrow[i], mx);
            float corr = __expf(mrow[i] - mn);
            mrow[i] = mn;
            float rs = 0.f;
            #pragma unroll
            for (int j = 0; j < 4; j++) {
                float p = __expf(s[i][j] - mn);
                s[i][j] = p; rs += p;
            }
            #pragma unroll
            for (int off = 8; off; off >>= 1)
                rs += __shfl_xor_sync(0xffffffffu, rs, off);
            lrow[i] = lrow[i] * corr + rs;
            #pragma unroll
            for (int j = 0; j < 4; j++) {
                o[i][j] *= corr;
                Ps[(i0 + i) * 64 + j0 + j] = s[i][j];
            }
        }
        __syncthreads();

        for (int kk = 0; kk < 64; kk++) {
            float pr[4];
            #pragma unroll
            for (int i = 0; i < 4; i++) pr[i] = Ps[(i0 + i) * 64 + kk];
            float4 vv = *(const float4*)(&Vs[kk * 64 + j0]);
            #pragma unroll
            for (int i = 0; i < 4; i++) {
                o[i][0] = fmaf(pr[i], vv.x, o[i][0]);
                o[i][1] = fmaf(pr[i], vv.y, o[i][1]);
                o[i][2] = fmaf(pr[i], vv.z, o[i][2]);
                o[i][3] = fmaf(pr[i], vv.w, o[i][3]);
            }
        }
    }

    #pragma unroll
    for (int i = 0; i < 4; i++) {
        float inv = 1.0f / lrow[i];
        int sidx = qt * 64 + i0 + i;
        size_t base = ((size_t)b * S_ + sidx) * E_ + h * DH_ + j0;
        __nv_bfloat16 hh[4], ll[4];
        #pragma unroll
        for (int j = 0; j < 4; j++) {
            float v = o[i][j] * inv;
            hh[j] = __float2bfloat16(v);
            ll[j] = __float2bfloat16(v - __bfloat162float(hh[j]));
        }
        *(__nv_bfloat162*)(Ohi + base)     = __halves2bfloat162(hh[0], hh[1]);
        *(__nv_bfloat162*)(Ohi + base + 2) = __halves2bfloat162(hh[2], hh[3]);
        *(__nv_bfloat162*)(Olo + base)     = __halves2bfloat162(ll[0], ll[1]);
        *(__nv_bfloat162*)(Olo + base + 2) = __halves2bfloat162(ll[2], ll[3]);
    }
}

// ---------------- host launcher ----------------
extern "C" void kernel_launch(void* const* d_in, const int* in_sizes, int n_in,
                              void* d_out, int out_size)
{
    const float* x   = (const float*)d_in[0];
    const float* Wq  = (const float*)d_in[1];
    const float* Wk  = (const float*)d_in[2];
    const float* Wv  = (const float*)d_in[3];
    const float* Wo  = (const float*)d_in[4];
    const float* bo  = (const float*)d_in[5];
    const float* W1  = (const float*)d_in[6];
    const float* b1  = (const float*)d_in[7];
    const float* W2  = (const float*)d_in[8];
    const float* b2  = (const float*)d_in[9];
    const float* g1  = (const float*)d_in[10];
    const float* be1 = (const float*)d_in[11];
    const float* g2  = (const float*)d_in[12];
    const float* be2 = (const float*)d_in[13];
    float* out = (float*)d_out;

    void *nx_hi, *nx_lo, *wqkv_hi, *wqkv_lo, *wo_hi, *wo_lo, *w1_hi, *w1_lo,
         *w2_hi, *w2_lo, *q, *k, *v, *attn_hi, *attn_lo, *x1, *nx2_hi, *nx2_lo,
         *ffn_hi, *ffn_lo;
    cudaGetSymbolAddress(&nx_hi, g_nx_hi);   cudaGetSymbolAddress(&nx_lo, g_nx_lo);
    cudaGetSymbolAddress(&wqkv_hi, g_wqkv_hi); cudaGetSymbolAddress(&wqkv_lo, g_wqkv_lo);
    cudaGetSymbolAddress(&wo_hi, g_wo_hi);   cudaGetSymbolAddress(&wo_lo, g_wo_lo);
    cudaGetSymbolAddress(&w1_hi, g_w1_hi);   cudaGetSymbolAddress(&w1_lo, g_w1_lo);
    cudaGetSymbolAddress(&w2_hi, g_w2_hi);   cudaGetSymbolAddress(&w2_lo, g_w2_lo);
    cudaGetSymbolAddress(&q, g_q); cudaGetSymbolAddress(&k, g_k); cudaGetSymbolAddress(&v, g_v);
    cudaGetSymbolAddress(&attn_hi, g_attn_hi); cudaGetSymbolAddress(&attn_lo, g_attn_lo);
    cudaGetSymbolAddress(&x1, g_x1);
    cudaGetSymbolAddress(&nx2_hi, g_nx2_hi); cudaGetSymbolAddress(&nx2_lo, g_nx2_lo);
    cudaGetSymbolAddress(&ffn_hi, g_ffn_hi); cudaGetSymbolAddress(&ffn_lo, g_ffn_lo);

    cudaFuncSetAttribute(gemm_mma_kernel<0>, cudaFuncAttributeMaxDynamicSharedMemorySize, GEMM_SMEM);
    cudaFuncSetAttribute(gemm_mma_kernel<1>, cudaFuncAttributeMaxDynamicSharedMemorySize, GEMM_SMEM);
    cudaFuncSetAttribute(gemm_mma_kernel<2>, cudaFuncAttributeMaxDynamicSharedMemorySize, GEMM_SMEM);
    cudaFuncSetAttribute(gemm_mma_kernel<3>, cudaFuncAttributeMaxDynamicSharedMemorySize, GEMM_SMEM);
    const int FLASH_SMEM = (4096 + 4160 + 4096 + 4096) * 4;
    cudaFuncSetAttribute(flash_kernel, cudaFuncAttributeMaxDynamicSharedMemorySize, FLASH_SMEM);

    // 1. weight transpose+split
    wqkv_split_kernel<<<dim3(E_/32, NQKV/32), 256>>>(Wq, Wk, Wv,
        (__nv_bfloat16*)wqkv_hi, (__nv_bfloat16*)wqkv_lo);
    wt_split_kernel<<<dim3(E_/32, E_/32), 256>>>(Wo, E_, E_,
        (__nv_bfloat16*)wo_hi, (__nv_bfloat16*)wo_lo);
    wt_split_kernel<<<dim3(E_/32, FF_/32), 256>>>(W1, E_, FF_,
        (__nv_bfloat16*)w1_hi, (__nv_bfloat16*)w1_lo);
    wt_split_kernel<<<dim3(FF_/32, E_/32), 256>>>(W2, FF_, E_,
        (__nv_bfloat16*)w2_hi, (__nv_bfloat16*)w2_lo);
    // 2. LN1 (+split)
    ln_split_kernel<<<TOK, 256>>>(x, g1, be1,
        (__nv_bfloat16*)nx_hi, (__nv_bfloat16*)nx_lo);
    // 3. fused QKV GEMM (N=3072) -> q,k,v
    gemm_mma_kernel<0><<<dim3(NQKV/128, TOK/128), 256, GEMM_SMEM>>>(
        (__nv_bfloat16*)nx_hi, (__nv_bfloat16*)nx_lo,
        (__nv_bfloat16*)wqkv_hi, (__nv_bfloat16*)wqkv_lo,
        nullptr, nullptr, (float*)q, (float*)k, (float*)v, nullptr, nullptr,
        E_, 0);
    // 4. flash attention -> attn hi/lo
    flash_kernel<<<dim3(S_/64, H_, B_), 256, FLASH_SMEM>>>(
        (float*)q, (float*)k, (float*)v,
        (__nv_bfloat16*)attn_hi, (__nv_bfloat16*)attn_lo);
    // 5. output projection + residual -> x1
    gemm_mma_kernel<1><<<dim3(E_/128, TOK/128), 256, GEMM_SMEM>>>(
        (__nv_bfloat16*)attn_hi, (__nv_bfloat16*)attn_lo,
        (__nv_bfloat16*)wo_hi, (__nv_bfloat16*)wo_lo,
        bo, x, (float*)x1, nullptr, nullptr, nullptr, nullptr,
        E_, E_);
    // 6. LN2 (+split)
    ln_split_kernel<<<TOK, 256>>>((float*)x1, g2, be2,
        (__nv_bfloat16*)nx2_hi, (__nv_bfloat16*)nx2_lo);
    // 7. FFN1: relu(+b1) -> ffn hi/lo
    gemm_mma_kernel<2><<<dim3(FF_/128, TOK/128), 256, GEMM_SMEM>>>(
        (__nv_bfloat16*)nx2_hi, (__nv_bfloat16*)nx2_lo,
        (__nv_bfloat16*)w1_hi, (__nv_bfloat16*)w1_lo,
        b1, nullptr, nullptr, nullptr, nullptr,
        (__nv_bfloat16*)ffn_hi, (__nv_bfloat16*)ffn_lo,
        E_, FF_);
    // 8. FFN2: +b2 +x1 -> out
    gemm_mma_kernel<3><<<dim3(E_/128, TOK/128), 256, GEMM_SMEM>>>(
        (__nv_bfloat16*)ffn_hi, (__nv_bfloat16*)ffn_lo,
        (__nv_bfloat16*)w2_hi, (__nv_bfloat16*)w2_lo,
        b2, (float*)x1, out, nullptr, nullptr, nullptr, nullptr,
        FF_, E_);
}

// round 6
// speedup vs baseline: 1.4907x; 1.4907x over previous
#include <cuda_runtime.h>
#include <cuda_fp16.h>
#include <cstdint>

#define B_   2
#define S_   2048
#define E_   1024
#define H_   16
#define DH_  64
#define FF_  4096
#define TOK  (B_*S_)   // 4096
#define NQKV 3072

// ---------------- scratch (no allocs allowed) ----------------
__device__ __half g_nx   [TOK*(size_t)E_];
__device__ __half g_wqkv_hi[(size_t)NQKV*E_], g_wqkv_lo[(size_t)NQKV*E_];
__device__ __half g_wo_hi [(size_t)E_*E_],   g_wo_lo [(size_t)E_*E_];
__device__ __half g_w1_hi [(size_t)FF_*E_],  g_w1_lo [(size_t)FF_*E_];
__device__ __half g_w2_hi [(size_t)E_*FF_],  g_w2_lo [(size_t)E_*FF_];
__device__ float g_q[(size_t)B_*H_*S_*DH_];
__device__ float g_k[(size_t)B_*H_*S_*DH_];
__device__ float g_v[(size_t)B_*H_*S_*DH_];
__device__ __half g_attn[TOK*(size_t)E_];
__device__ float g_x1[TOK*(size_t)E_];
__device__ __half g_nx2 [TOK*(size_t)E_];
__device__ __half g_ffn [TOK*(size_t)FF_];

__device__ __forceinline__ float neg_inf() { return __int_as_float(0xff800000u); }

// ---------------- PTX helpers (base-target-safe: sm_80 features) -------------
__device__ __forceinline__ uint32_t smem_u32(const void* p) {
    uint32_t a;
    asm("{ .reg .u64 t; cvta.to.shared.u64 t, %1; cvt.u32.u64 %0, t; }" : "=r"(a) : "l"(p));
    return a;
}
__device__ __forceinline__ void cp16(uint32_t s, const void* g) {
    asm volatile("cp.async.cg.shared.global [%0], [%1], 16;" :: "r"(s), "l"(g));
}
#define CP_COMMIT() asm volatile("cp.async.commit_group;" ::: "memory")
#define CP_WAIT(n)  asm volatile("cp.async.wait_group %0;" :: "n"(n) : "memory")

__device__ __forceinline__ void ldm_x4(uint32_t& r0, uint32_t& r1, uint32_t& r2,
                                       uint32_t& r3, uint32_t a) {
    asm volatile("ldmatrix.sync.aligned.m8n8.x4.shared.b16 {%0,%1,%2,%3}, [%4];"
                 : "=r"(r0), "=r"(r1), "=r"(r2), "=r"(r3) : "r"(a));
}
__device__ __forceinline__ void mma16816(float* c, uint32_t a0, uint32_t a1,
                                         uint32_t a2, uint32_t a3,
                                         uint32_t b0, uint32_t b1) {
    asm volatile(
        "mma.sync.aligned.m16n8k16.row.col.f32.f16.f16.f32 "
        "{%0,%1,%2,%3},{%4,%5,%6,%7},{%8,%9},{%0,%1,%2,%3};"
        : "+f"(c[0]), "+f"(c[1]), "+f"(c[2]), "+f"(c[3])
        : "r"(a0), "r"(a1), "r"(a2), "r"(a3), "r"(b0), "r"(b1));
}

// ---------------- LayerNorm -> fp16: one block per token ---------------------
__global__ void __launch_bounds__(256) ln_fp16_kernel(
    const float* __restrict__ x, const float* __restrict__ g,
    const float* __restrict__ bta, __half* __restrict__ o)
{
    __shared__ float sh1[8], sh2[8];
    int tok = blockIdx.x;
    int t = threadIdx.x;
    const float4* xr = (const float4*)(x + (size_t)tok * E_);
    float4 v = xr[t];
    float sum = v.x + v.y + v.z + v.w;
    float sq  = v.x*v.x + v.y*v.y + v.z*v.z + v.w*v.w;
    #pragma unroll
    for (int o2 = 16; o2 > 0; o2 >>= 1) {
        sum += __shfl_xor_sync(0xffffffffu, sum, o2);
        sq  += __shfl_xor_sync(0xffffffffu, sq,  o2);
    }
    if ((t & 31) == 0) { sh1[t >> 5] = sum; sh2[t >> 5] = sq; }
    __syncthreads();
    if (t < 32) {
        sum = (t < 8) ? sh1[t] : 0.f;
        sq  = (t < 8) ? sh2[t] : 0.f;
        #pragma unroll
        for (int o2 = 4; o2 > 0; o2 >>= 1) {
            sum += __shfl_xor_sync(0xffffffffu, sum, o2);
            sq  += __shfl_xor_sync(0xffffffffu, sq,  o2);
        }
        if (t == 0) { sh1[0] = sum; sh2[0] = sq; }
    }
    __syncthreads();
    sum = sh1[0]; sq = sh2[0];
    float mu  = sum * (1.0f / E_);
    float var = sq * (1.0f / E_) - mu * mu;
    float rs  = rsqrtf(var + 1e-5f);
    float4 gv = ((const float4*)g)[t];
    float4 bv = ((const float4*)bta)[t];
    float a0 = (v.x - mu) * rs * gv.x + bv.x;
    float a1 = (v.y - mu) * rs * gv.y + bv.y;
    float a2 = (v.z - mu) * rs * gv.z + bv.z;
    float a3 = (v.w - mu) * rs * gv.w + bv.w;
    size_t base = (size_t)tok * E_ + t * 4;
    *(__half2*)(o + base)     = __floats2half2_rn(a0, a1);
    *(__half2*)(o + base + 2) = __floats2half2_rn(a2, a3);
}

// ---------------- weight transpose + fp16 split: W[K,N] -> Wt[N,K] hi/lo -----
__global__ void __launch_bounds__(256) wt_split_kernel(
    const float* __restrict__ W, int K, int N,
    __half* __restrict__ ohi, __half* __restrict__ olo)
{
    __shared__ float t[32][33];
    int k0 = blockIdx.x * 32, n0 = blockIdx.y * 32;
    int tx = threadIdx.x & 31, ty = threadIdx.x >> 5;
    #pragma unroll
    for (int r = 0; r < 4; r++)
        t[ty + 8*r][tx] = W[(size_t)(k0 + ty + 8*r) * N + n0 + tx];
    __syncthreads();
    #pragma unroll
    for (int r = 0; r < 4; r++) {
        float v = t[tx][ty + 8*r];
        __half h = __float2half_rn(v);
        __half l = __float2half_rn(v - __half2float(h));
        size_t o = (size_t)(n0 + ty + 8*r) * K + k0 + tx;
        ohi[o] = h; olo[o] = l;
    }
}

// QKV weights [H,E,DH] x3 -> fused Wt[3072, E] hi/lo
__global__ void __launch_bounds__(256) wqkv_split_kernel(
    const float* __restrict__ Wq, const float* __restrict__ Wk,
    const float* __restrict__ Wv,
    __half* __restrict__ ohi, __half* __restrict__ olo)
{
    __shared__ float t[32][33];
    int e0 = blockIdx.x * 32, n0 = blockIdx.y * 32;
    const float* Wm = (n0 < 1024) ? Wq : (n0 < 2048) ? Wk : Wv;
    int nn = n0 & 1023;
    int h = nn >> 6, d0 = nn & 63;
    int tx = threadIdx.x & 31, ty = threadIdx.x >> 5;
    #pragma unroll
    for (int r = 0; r < 4; r++)
        t[ty + 8*r][tx] = Wm[((size_t)h * E_ + e0 + ty + 8*r) * DH_ + d0 + tx];
    __syncthreads();
    #pragma unroll
    for (int r = 0; r < 4; r++) {
        float v = t[tx][ty + 8*r];
        __half hh = __float2half_rn(v);
        __half ll = __float2half_rn(v - __half2float(hh));
        size_t o = (size_t)(n0 + ty + 8*r) * E_ + e0 + tx;
        ohi[o] = hh; olo[o] = ll;
    }
}

// ---------------- HMMA GEMM: C[M,N] = A[M,K]*Bt[N,K]^T, weight hi/lo 2-pass ---
// Virtual K = 2K via slabs: (A,Bhi) then (A,Blo)
// MODE 0: QKV scatter to q/k/v [B,H,S,DH]
// MODE 1/3: + bias + res -> o0 fp32
// MODE 2: relu(+bias) -> oh fp16
#define BK     32
#define LDS    40
#define AELEMS (128 * LDS)
#define ABYTES (AELEMS * 2)            // 10240
#define STG_BYTES (2 * ABYTES)
#define GEMM_SMEM (4 * STG_BYTES)      // 81920 -> 2 CTA/SM

template<int MODE>
__global__ void __launch_bounds__(256, 2) gemm_mma_kernel(
    const __half* __restrict__ A,
    const __half* __restrict__ Bhi, const __half* __restrict__ Blo,
    const float* __restrict__ bias, const float* __restrict__ res,
    float* __restrict__ o0, float* __restrict__ o1, float* __restrict__ o2,
    __half* __restrict__ oh,
    int K, int ldC)
{
    extern __shared__ __half smbuf[];
    const uint32_t sbase = smem_u32(smbuf);
    const int NIT = 2 * K / BK;
    const int t = threadIdx.x;
    const int wid = t >> 5, lane = t & 31;
    const int bm = blockIdx.y * 128, bn = blockIdx.x * 128;
    const int wm = (wid & 1) * 64, wn = (wid >> 1) * 32;

    auto aptr = [&](int i) -> const __half* {
        int kc = i * BK;
        return A + (size_t)bm * K + (kc & (K - 1));
    };
    auto bptr = [&](int i) -> const __half* {
        int kc = i * BK;
        const __half* s = (kc >= K) ? Blo : Bhi;
        return s + (size_t)bn * K + (kc & (K - 1));
    };
    auto load_stage = [&](int st, const __half* Ap, const __half* Bp) {
        uint32_t sa = sbase + st * STG_BYTES;
        #pragma unroll
        for (int p = 0; p < 2; p++) {
            int idx = t + p * 256;
            int row = idx >> 2, ch = idx & 3;
            uint32_t off = (uint32_t)(row * LDS + ch * 8) * 2;
            cp16(sa + off,          Ap + (size_t)row * K + ch * 8);
            cp16(sa + ABYTES + off, Bp + (size_t)row * K + ch * 8);
        }
    };

    #pragma unroll
    for (int s = 0; s < 3; s++) { load_stage(s, aptr(s), bptr(s)); CP_COMMIT(); }

    float c[4][4][4];
    #pragma unroll
    for (int mt = 0; mt < 4; mt++)
        #pragma unroll
        for (int nt = 0; nt < 4; nt++)
            #pragma unroll
            for (int e = 0; e < 4; e++) c[mt][nt][e] = 0.f;

    for (int i = 0; i < NIT; i++) {
        CP_WAIT(2);
        __syncthreads();
        if (i + 3 < NIT) load_stage((i + 3) & 3, aptr(i + 3), bptr(i + 3));
        CP_COMMIT();

        uint32_t sa = sbase + (i & 3) * STG_BYTES;
        uint32_t sb = sa + ABYTES;
        #pragma unroll
        for (int ks = 0; ks < 2; ks++) {
            uint32_t a[4][4];
            #pragma unroll
            for (int mt = 0; mt < 4; mt++) {
                uint32_t addr = sa + (uint32_t)(((wm + mt*16 + (lane & 15)) * LDS
                                  + ks*16 + (lane >> 4) * 8) * 2);
                ldm_x4(a[mt][0], a[mt][1], a[mt][2], a[mt][3], addr);
            }
            uint32_t b[4][2];
            #pragma unroll
            for (int np = 0; np < 2; np++) {
                int nrow = wn + np*16 + (lane & 7) + ((lane >> 4) << 3);
                int ncol = ks*16 + (((lane >> 3) & 1) << 3);
                uint32_t addr = sb + (uint32_t)((nrow * LDS + ncol) * 2);
                uint32_t r0, r1, r2, r3;
                ldm_x4(r0, r1, r2, r3, addr);
                b[2*np][0] = r0; b[2*np][1] = r1;
                b[2*np+1][0] = r2; b[2*np+1][1] = r3;
            }
            #pragma unroll
            for (int mt = 0; mt < 4; mt++)
                #pragma unroll
                for (int nt = 0; nt < 4; nt++)
                    mma16816(c[mt][nt], a[mt][0], a[mt][1], a[mt][2], a[mt][3],
                             b[nt][0], b[nt][1]);
        }
    }

    // ---------------- epilogue ----------------
    const int r = lane >> 2, cq = (lane & 3) * 2;
    #pragma unroll
    for (int mt = 0; mt < 4; mt++) {
        #pragma unroll
        for (int half_ = 0; half_ < 2; half_++) {
            int m = bm + wm + mt * 16 + r + half_ * 8;
            #pragma unroll
            for (int nt = 0; nt < 4; nt++) {
                int n = bn + wn + nt * 8 + cq;
                float v0 = c[mt][nt][half_ * 2 + 0];
                float v1 = c[mt][nt][half_ * 2 + 1];
                if (MODE == 0) {
                    int mat = n >> 10;
                    float* qkv = (mat == 0) ? o0 : (mat == 1) ? o1 : o2;
                    int hh = (n & 1023) >> 6, d = n & 63;
                    int bb = m >> 11, srow = m & (S_ - 1);
                    float* p = qkv + (((size_t)(bb * H_ + hh) * S_ + srow) << 6) + d;
                    *(float2*)p = make_float2(v0, v1);
                } else if (MODE == 2) {
                    float2 bv = *(const float2*)(bias + n);
                    v0 = fmaxf(v0 + bv.x, 0.f);
                    v1 = fmaxf(v1 + bv.y, 0.f);
                    *(__half2*)(oh + (size_t)m * ldC + n) = __floats2half2_rn(v0, v1);
                } else {
                    size_t base = (size_t)m * ldC + n;
                    float2 bv = *(const float2*)(bias + n);
                    float2 rv = *(const float2*)(res + base);
                    *(float2*)(o0 + base) = make_float2(v0 + bv.x + rv.x,
                                                        v1 + bv.y + rv.y);
                }
            }
        }
    }
}

// ---------------- flash attention (causal), 64x64 tiles, fp16 output ----------
__global__ void __launch_bounds__(256) flash_kernel(
    const float* __restrict__ Q, const float* __restrict__ Kp,
    const float* __restrict__ Vp, __half* __restrict__ O)
{
    extern __shared__ float sm[];
    float* Qs = sm;             // [64][64]
    float* Ks = sm + 4096;      // [kk][j] stride 65
    float* Vs = Ks + 4160;      // [key][dim] stride 64
    float* Ps = Vs + 4096;      // [i][k] stride 64

    int qt = blockIdx.x, h = blockIdx.y, b = blockIdx.z;
    int t = threadIdx.x, tx = t & 15, ty = t >> 4;
    int i0 = ty * 4, j0 = tx * 4;

    const float* Qg = Q  + (((size_t)(b * H_ + h)) * S_ + qt * 64) * DH_;
    const float* Kg = Kp + ((size_t)(b * H_ + h)) * S_ * DH_;
    const float* Vg = Vp + ((size_t)(b * H_ + h)) * S_ * DH_;

    for (int i = t; i < 1024; i += 256)
        ((float4*)Qs)[i] = ((const float4*)Qg)[i];

    float mrow[4], lrow[4], o[4][4];
    #pragma unroll
    for (int i = 0; i < 4; i++) {
        mrow[i] = neg_inf(); lrow[i] = 0.f;
        #pragma unroll
        for (int j = 0; j < 4; j++) o[i][j] = 0.f;
    }

    for (int kt = 0; kt <= qt; kt++) {
        __syncthreads();
        const float* kg = Kg + (size_t)kt * 64 * DH_;
        for (int idx = t; idx < 4096; idx += 256)
            Ks[(idx & 63) * 65 + (idx >> 6)] = kg[idx];
        const float* vg = Vg + (size_t)kt * 64 * DH_;
        for (int i = t; i < 1024; i += 256)
            ((float4*)Vs)[i] = ((const float4*)vg)[i];
        __syncthreads();

        float s[4][4];
        #pragma unroll
        for (int i = 0; i < 4; i++)
            #pragma unroll
            for (int j = 0; j < 4; j++) s[i][j] = 0.f;

        for (int kk = 0; kk < 64; kk++) {
            float qr[4], kr[4];
            #pragma unroll
            for (int i = 0; i < 4; i++) qr[i] = Qs[(i0 + i) * 64 + kk];
            #pragma unroll
            for (int j = 0; j < 4; j++) kr[j] = Ks[kk * 65 + j0 + j];
            #pragma unroll
            for (int i = 0; i < 4; i++)
                #pragma unroll
                for (int j = 0; j < 4; j++)
                    s[i][j] = fmaf(qr[i], kr[j], s[i][j]);
        }
        #pragma unroll
        for (int i = 0; i < 4; i++)
            #pragma unroll
            for (int j = 0; j < 4; j++) s[i][j] *= 0.125f;

        if (kt == qt) {
            #pragma unroll
            for (int i = 0; i < 4; i++)
                #pragma unroll
                for (int j = 0; j < 4; j++)
                    if (j0 + j > i0 + i) s[i][j] = neg_inf();
        }

        #pragma unroll
        for (int i = 0; i < 4; i++) {
            float mx = fmaxf(fmaxf(s[i][0], s[i][1]), fmaxf(s[i][2], s[i][3]));
            #pragma unroll
            for (int off = 8; off; off >>= 1)
                mx = fmaxf(mx, __shfl_xor_sync(0xffffffffu, mx, off));
            float mn = fmaxf(mrow[i], mx);
            float corr = __expf(mrow[i] - mn);
            mrow[i] = mn;
            float rs = 0.f;
            #pragma unroll
            for (int j = 0; j < 4; j++) {
                float p = __expf(s[i][j] - mn);
                s[i][j] = p; rs += p;
            }
            #pragma unroll
            for (int off = 8; off; off >>= 1)
                rs += __shfl_xor_sync(0xffffffffu, rs, off);
            lrow[i] = lrow[i] * corr + rs;
            #pragma unroll
            for (int j = 0; j < 4; j++) {
                o[i][j] *= corr;
                Ps[(i0 + i) * 64 + j0 + j] = s[i][j];
            }
        }
        __syncthreads();

        for (int kk = 0; kk < 64; kk++) {
            float pr[4];
            #pragma unroll
            for (int i = 0; i < 4; i++) pr[i] = Ps[(i0 + i) * 64 + kk];
            float4 vv = *(const float4*)(&Vs[kk * 64 + j0]);
            #pragma unroll
            for (int i = 0; i < 4; i++) {
                o[i][0] = fmaf(pr[i], vv.x, o[i][0]);
                o[i][1] = fmaf(pr[i], vv.y, o[i][1]);
                o[i][2] = fmaf(pr[i], vv.z, o[i][2]);
                o[i][3] = fmaf(pr[i], vv.w, o[i][3]);
            }
        }
    }

    #pragma unroll
    for (int i = 0; i < 4; i++) {
        float inv = 1.0f / lrow[i];
        int sidx = qt * 64 + i0 + i;
        size_t base = ((size_t)b * S_ + sidx) * E_ + h * DH_ + j0;
        *(__half2*)(O + base)     = __floats2half2_rn(o[i][0]*inv, o[i][1]*inv);
        *(__half2*)(O + base + 2) = __floats2half2_rn(o[i][2]*inv, o[i][3]*inv);
    }
}

// ---------------- host launcher ----------------
extern "C" void kernel_launch(void* const* d_in, const int* in_sizes, int n_in,
                              void* d_out, int out_size)
{
    const float* x   = (const float*)d_in[0];
    const float* Wq  = (const float*)d_in[1];
    const float* Wk  = (const float*)d_in[2];
    const float* Wv  = (const float*)d_in[3];
    const float* Wo  = (const float*)d_in[4];
    const float* bo  = (const float*)d_in[5];
    const float* W1  = (const float*)d_in[6];
    const float* b1  = (const float*)d_in[7];
    const float* W2  = (const float*)d_in[8];
    const float* b2  = (const float*)d_in[9];
    const float* g1  = (const float*)d_in[10];
    const float* be1 = (const float*)d_in[11];
    const float* g2  = (const float*)d_in[12];
    const float* be2 = (const float*)d_in[13];
    float* out = (float*)d_out;

    void *nx, *wqkv_hi, *wqkv_lo, *wo_hi, *wo_lo, *w1_hi, *w1_lo, *w2_hi, *w2_lo,
         *q, *k, *v, *attn, *x1, *nx2, *ffn;
    cudaGetSymbolAddress(&nx, g_nx);
    cudaGetSymbolAddress(&wqkv_hi, g_wqkv_hi); cudaGetSymbolAddress(&wqkv_lo, g_wqkv_lo);
    cudaGetSymbolAddress(&wo_hi, g_wo_hi);   cudaGetSymbolAddress(&wo_lo, g_wo_lo);
    cudaGetSymbolAddress(&w1_hi, g_w1_hi);   cudaGetSymbolAddress(&w1_lo, g_w1_lo);
    cudaGetSymbolAddress(&w2_hi, g_w2_hi);   cudaGetSymbolAddress(&w2_lo, g_w2_lo);
    cudaGetSymbolAddress(&q, g_q); cudaGetSymbolAddress(&k, g_k); cudaGetSymbolAddress(&v, g_v);
    cudaGetSymbolAddress(&attn, g_attn);
    cudaGetSymbolAddress(&x1, g_x1);
    cudaGetSymbolAddress(&nx2, g_nx2);
    cudaGetSymbolAddress(&ffn, g_ffn);

    cudaFuncSetAttribute(gemm_mma_kernel<0>, cudaFuncAttributeMaxDynamicSharedMemorySize, GEMM_SMEM);
    cudaFuncSetAttribute(gemm_mma_kernel<1>, cudaFuncAttributeMaxDynamicSharedMemorySize, GEMM_SMEM);
    cudaFuncSetAttribute(gemm_mma_kernel<2>, cudaFuncAttributeMaxDynamicSharedMemorySize, GEMM_SMEM);
    cudaFuncSetAttribute(gemm_mma_kernel<3>, cudaFuncAttributeMaxDynamicSharedMemorySize, GEMM_SMEM);
    const int FLASH_SMEM = (4096 + 4160 + 4096 + 4096) * 4;
    cudaFuncSetAttribute(flash_kernel, cudaFuncAttributeMaxDynamicSharedMemorySize, FLASH_SMEM);

    // 1. weight transpose+split (fp16 hi/lo)
    wqkv_split_kernel<<<dim3(E_/32, NQKV/32), 256>>>(Wq, Wk, Wv,
        (__half*)wqkv_hi, (__half*)wqkv_lo);
    wt_split_kernel<<<dim3(E_/32, E_/32), 256>>>(Wo, E_, E_,
        (__half*)wo_hi, (__half*)wo_lo);
    wt_split_kernel<<<dim3(E_/32, FF_/32), 256>>>(W1, E_, FF_,
        (__half*)w1_hi, (__half*)w1_lo);
    wt_split_kernel<<<dim3(FF_/32, E_/32), 256>>>(W2, FF_, E_,
        (__half*)w2_hi, (__half*)w2_lo);
    // 2. LN1 -> fp16
    ln_fp16_kernel<<<TOK, 256>>>(x, g1, be1, (__half*)nx);
    // 3. fused QKV GEMM (N=3072) -> q,k,v fp32
    gemm_mma_kernel<0><<<dim3(NQKV/128, TOK/128), 256, GEMM_SMEM>>>(
        (__half*)nx, (__half*)wqkv_hi, (__half*)wqkv_lo,
        nullptr, nullptr, (float*)q, (float*)k, (float*)v, nullptr, E_, 0);
    // 4. flash attention -> attn fp16
    flash_kernel<<<dim3(S_/64, H_, B_), 256, FLASH_SMEM>>>(
        (float*)q, (float*)k, (float*)v, (__half*)attn);
    // 5. output projection + residual -> x1 fp32
    gemm_mma_kernel<1><<<dim3(E_/128, TOK/128), 256, GEMM_SMEM>>>(
        (__half*)attn, (__half*)wo_hi, (__half*)wo_lo,
        bo, x, (float*)x1, nullptr, nullptr, nullptr, E_, E_);
    // 6. LN2 -> fp16
    ln_fp16_kernel<<<TOK, 256>>>((float*)x1, g2, be2, (__half*)nx2);
    // 7. FFN1: relu(+b1) -> ffn fp16
    gemm_mma_kernel<2><<<dim3(FF_/128, TOK/128), 256, GEMM_SMEM>>>(
        (__half*)nx2, (__half*)w1_hi, (__half*)w1_lo,
        b1, nullptr, nullptr, nullptr, nullptr, (__half*)ffn, E_, FF_);
    // 8. FFN2: +b2 +x1 -> out
    gemm_mma_kernel<3><<<dim3(E_/128, TOK/128), 256, GEMM_SMEM>>>(
        (__half*)ffn, (__half*)w2_hi, (__half*)w2_lo,
        b2, (float*)x1, out, nullptr, nullptr, nullptr, FF_, E_);
}

// round 8
// speedup vs baseline: 2.4084x; 1.6156x over previous
#include <cuda_runtime.h>
#include <cuda_fp16.h>
#include <cstdint>

#define B_   2
#define S_   2048
#define E_   1024
#define H_   16
#define DH_  64
#define FF_  4096
#define TOK  (B_*S_)   // 4096
#define NQKV 3072

// ---------------- scratch (no allocs allowed) ----------------
__device__ __half g_nx   [TOK*(size_t)E_];
__device__ __half g_wqkv_hi[(size_t)NQKV*E_], g_wqkv_lo[(size_t)NQKV*E_];
__device__ __half g_wo_hi [(size_t)E_*E_],   g_wo_lo [(size_t)E_*E_];
__device__ __half g_w1_hi [(size_t)FF_*E_],  g_w1_lo [(size_t)FF_*E_];
__device__ __half g_w2_hi [(size_t)E_*FF_],  g_w2_lo [(size_t)E_*FF_];
__device__ __half g_q [(size_t)B_*H_*S_*DH_];
__device__ __half g_k [(size_t)B_*H_*S_*DH_];
__device__ __half g_vt[(size_t)B_*H_*DH_*S_];   // V transposed: [B,H,DH,S]
__device__ __half g_attn[TOK*(size_t)E_];
__device__ float g_x1[TOK*(size_t)E_];
__device__ __half g_nx2 [TOK*(size_t)E_];
__device__ __half g_ffn [TOK*(size_t)FF_];

// ---------------- PTX helpers (base-target-safe: sm_80 features) -------------
__device__ __forceinline__ uint32_t smem_u32(const void* p) {
    uint32_t a;
    asm("{ .reg .u64 t; cvta.to.shared.u64 t, %1; cvt.u32.u64 %0, t; }" : "=r"(a) : "l"(p));
    return a;
}
__device__ __forceinline__ uint32_t h2_as_u32(__half2 h) {
    union { __half2 h2; uint32_t u; } cvt;
    cvt.h2 = h;
    return cvt.u;
}
__device__ __forceinline__ void cp16(uint32_t s, const void* g) {
    asm volatile("cp.async.cg.shared.global [%0], [%1], 16;" :: "r"(s), "l"(g));
}
#define CP_COMMIT() asm volatile("cp.async.commit_group;" ::: "memory")
#define CP_WAIT(n)  asm volatile("cp.async.wait_group %0;" :: "n"(n) : "memory")

__device__ __forceinline__ void ldm_x4(uint32_t& r0, uint32_t& r1, uint32_t& r2,
                                       uint32_t& r3, uint32_t a) {
    asm volatile("ldmatrix.sync.aligned.m8n8.x4.shared.b16 {%0,%1,%2,%3}, [%4];"
                 : "=r"(r0), "=r"(r1), "=r"(r2), "=r"(r3) : "r"(a));
}
__device__ __forceinline__ void mma16816(float* c, uint32_t a0, uint32_t a1,
                                         uint32_t a2, uint32_t a3,
                                         uint32_t b0, uint32_t b1) {
    asm volatile(
        "mma.sync.aligned.m16n8k16.row.col.f32.f16.f16.f32 "
        "{%0,%1,%2,%3},{%4,%5,%6,%7},{%8,%9},{%0,%1,%2,%3};"
        : "+f"(c[0]), "+f"(c[1]), "+f"(c[2]), "+f"(c[3])
        : "r"(a0), "r"(a1), "r"(a2), "r"(a3), "r"(b0), "r"(b1));
}

// fast 2^x on the FMA pipe (no MUFU). x clamped to [-125, ~0]. rel err ~1e-7.
__device__ __forceinline__ float fexp2(float x) {
    x = fmaxf(x, -125.0f);
    float t = x + 12582912.0f;              // 1.5*2^23: round-to-int in mantissa
    int n = __float_as_int(t) - 0x4B400000; // integer part
    float f = x - (t - 12582912.0f);        // frac in [-0.5, 0.5]
    float p =              1.5403530e-4f;
    p = fmaf(p, f, 1.3333558e-3f);
    p = fmaf(p, f, 9.6181291e-3f);
    p = fmaf(p, f, 5.5504109e-2f);
    p = fmaf(p, f, 2.4022651e-1f);
    p = fmaf(p, f, 6.9314718e-1f);
    p = fmaf(p, f, 1.0f);
    return p * __int_as_float((n + 127) << 23);
}

// ---------------- LayerNorm -> fp16: one block per token ---------------------
__global__ void __launch_bounds__(256) ln_fp16_kernel(
    const float* __restrict__ x, const float* __restrict__ g,
    const float* __restrict__ bta, __half* __restrict__ o)
{
    __shared__ float sh1[8], sh2[8];
    int tok = blockIdx.x;
    int t = threadIdx.x;
    const float4* xr = (const float4*)(x + (size_t)tok * E_);
    float4 v = xr[t];
    float sum = v.x + v.y + v.z + v.w;
    float sq  = v.x*v.x + v.y*v.y + v.z*v.z + v.w*v.w;
    #pragma unroll
    for (int o2 = 16; o2 > 0; o2 >>= 1) {
        sum += __shfl_xor_sync(0xffffffffu, sum, o2);
        sq  += __shfl_xor_sync(0xffffffffu, sq,  o2);
    }
    if ((t & 31) == 0) { sh1[t >> 5] = sum; sh2[t >> 5] = sq; }
    __syncthreads();
    if (t < 32) {
        sum = (t < 8) ? sh1[t] : 0.f;
        sq  = (t < 8) ? sh2[t] : 0.f;
        #pragma unroll
        for (int o2 = 4; o2 > 0; o2 >>= 1) {
            sum += __shfl_xor_sync(0xffffffffu, sum, o2);
            sq  += __shfl_xor_sync(0xffffffffu, sq,  o2);
        }
        if (t == 0) { sh1[0] = sum; sh2[0] = sq; }
    }
    __syncthreads();
    sum = sh1[0]; sq = sh2[0];
    float mu  = sum * (1.0f / E_);
    float var = sq * (1.0f / E_) - mu * mu;
    float rs  = rsqrtf(var + 1e-5f);
    float4 gv = ((const float4*)g)[t];
    float4 bv = ((const float4*)bta)[t];
    float a0 = (v.x - mu) * rs * gv.x + bv.x;
    float a1 = (v.y - mu) * rs * gv.y + bv.y;
    float a2 = (v.z - mu) * rs * gv.z + bv.z;
    float a3 = (v.w - mu) * rs * gv.w + bv.w;
    size_t base = (size_t)tok * E_ + t * 4;
    *(__half2*)(o + base)     = __floats2half2_rn(a0, a1);
    *(__half2*)(o + base + 2) = __floats2half2_rn(a2, a3);
}

// ---------------- weight transpose + fp16 split: W[K,N] -> Wt[N,K] hi/lo -----
__global__ void __launch_bounds__(256) wt_split_kernel(
    const float* __restrict__ W, int K, int N,
    __half* __restrict__ ohi, __half* __restrict__ olo)
{
    __shared__ float t[32][33];
    int k0 = blockIdx.x * 32, n0 = blockIdx.y * 32;
    int tx = threadIdx.x & 31, ty = threadIdx.x >> 5;
    #pragma unroll
    for (int r = 0; r < 4; r++)
        t[ty + 8*r][tx] = W[(size_t)(k0 + ty + 8*r) * N + n0 + tx];
    __syncthreads();
    #pragma unroll
    for (int r = 0; r < 4; r++) {
        float v = t[tx][ty + 8*r];
        __half h = __float2half_rn(v);
        __half l = __float2half_rn(v - __half2float(h));
        size_t o = (size_t)(n0 + ty + 8*r) * K + k0 + tx;
        ohi[o] = h; olo[o] = l;
    }
}

// QKV weights [H,E,DH] x3 -> fused Wt[3072, E] hi/lo
__global__ void __launch_bounds__(256) wqkv_split_kernel(
    const float* __restrict__ Wq, const float* __restrict__ Wk,
    const float* __restrict__ Wv,
    __half* __restrict__ ohi, __half* __restrict__ olo)
{
    __shared__ float t[32][33];
    int e0 = blockIdx.x * 32, n0 = blockIdx.y * 32;
    const float* Wm = (n0 < 1024) ? Wq : (n0 < 2048) ? Wk : Wv;
    int nn = n0 & 1023;
    int h = nn >> 6, d0 = nn & 63;
    int tx = threadIdx.x & 31, ty = threadIdx.x >> 5;
    #pragma unroll
    for (int r = 0; r < 4; r++)
        t[ty + 8*r][tx] = Wm[((size_t)h * E_ + e0 + ty + 8*r) * DH_ + d0 + tx];
    __syncthreads();
    #pragma unroll
    for (int r = 0; r < 4; r++) {
        float v = t[tx][ty + 8*r];
        __half hh = __float2half_rn(v);
        __half ll = __float2half_rn(v - __half2float(hh));
        size_t o = (size_t)(n0 + ty + 8*r) * E_ + e0 + tx;
        ohi[o] = hh; olo[o] = ll;
    }
}

// ---------------- HMMA GEMM: C[M,N] = A[M,K]*Bt[N,K]^T, weight hi/lo 2-pass ---
// MODE 0: QKV scatter: q,k fp16 [B,H,S,DH]; v fp16 transposed [B,H,DH,S]
// MODE 1/3: + bias + res -> o0 fp32
// MODE 2: relu(+bias) -> oh fp16
#define BK     32
#define LDS    40
#define AELEMS (128 * LDS)
#define ABYTES (AELEMS * 2)            // 10240
#define STG_BYTES (2 * ABYTES)
#define GEMM_SMEM (4 * STG_BYTES)      // 81920 -> 2 CTA/SM

template<int MODE>
__global__ void __launch_bounds__(256, 2) gemm_mma_kernel(
    const __half* __restrict__ A,
    const __half* __restrict__ Bhi, const __half* __restrict__ Blo,
    const float* __restrict__ bias, const float* __restrict__ res,
    float* __restrict__ o0, __half* __restrict__ oh,
    __half* __restrict__ q16, __half* __restrict__ k16, __half* __restrict__ v16,
    int K, int ldC)
{
    extern __shared__ __half smbuf[];
    const uint32_t sbase = smem_u32(smbuf);
    const int NIT = 2 * K / BK;
    const int t = threadIdx.x;
    const int wid = t >> 5, lane = t & 31;
    const int bm = blockIdx.y * 128, bn = blockIdx.x * 128;
    const int wm = (wid & 1) * 64, wn = (wid >> 1) * 32;

    auto aptr = [&](int i) -> const __half* {
        int kc = i * BK;
        return A + (size_t)bm * K + (kc & (K - 1));
    };
    auto bptr = [&](int i) -> const __half* {
        int kc = i * BK;
        const __half* s = (kc >= K) ? Blo : Bhi;
        return s + (size_t)bn * K + (kc & (K - 1));
    };
    auto load_stage = [&](int st, const __half* Ap, const __half* Bp) {
        uint32_t sa = sbase + st * STG_BYTES;
        #pragma unroll
        for (int p = 0; p < 2; p++) {
            int idx = t + p * 256;
            int row = idx >> 2, ch = idx & 3;
            uint32_t off = (uint32_t)(row * LDS + ch * 8) * 2;
            cp16(sa + off,          Ap + (size_t)row * K + ch * 8);
            cp16(sa + ABYTES + off, Bp + (size_t)row * K + ch * 8);
        }
    };

    #pragma unroll
    for (int s = 0; s < 3; s++) { load_stage(s, aptr(s), bptr(s)); CP_COMMIT(); }

    float c[4][4][4];
    #pragma unroll
    for (int mt = 0; mt < 4; mt++)
        #pragma unroll
        for (int nt = 0; nt < 4; nt++)
            #pragma unroll
            for (int e = 0; e < 4; e++) c[mt][nt][e] = 0.f;

    for (int i = 0; i < NIT; i++) {
        CP_WAIT(2);
        __syncthreads();
        if (i + 3 < NIT) load_stage((i + 3) & 3, aptr(i + 3), bptr(i + 3));
        CP_COMMIT();

        uint32_t sa = sbase + (i & 3) * STG_BYTES;
        uint32_t sb = sa + ABYTES;
        #pragma unroll
        for (int ks = 0; ks < 2; ks++) {
            uint32_t a[4][4];
            #pragma unroll
            for (int mt = 0; mt < 4; mt++) {
                uint32_t addr = sa + (uint32_t)(((wm + mt*16 + (lane & 15)) * LDS
                                  + ks*16 + (lane >> 4) * 8) * 2);
                ldm_x4(a[mt][0], a[mt][1], a[mt][2], a[mt][3], addr);
            }
            uint32_t b[4][2];
            #pragma unroll
            for (int np = 0; np < 2; np++) {
                int nrow = wn + np*16 + (lane & 7) + ((lane >> 4) << 3);
                int ncol = ks*16 + (((lane >> 3) & 1) << 3);
                uint32_t addr = sb + (uint32_t)((nrow * LDS + ncol) * 2);
                uint32_t r0, r1, r2, r3;
                ldm_x4(r0, r1, r2, r3, addr);
                b[2*np][0] = r0; b[2*np][1] = r1;
                b[2*np+1][0] = r2; b[2*np+1][1] = r3;
            }
            #pragma unroll
            for (int mt = 0; mt < 4; mt++)
                #pragma unroll
                for (int nt = 0; nt < 4; nt++)
                    mma16816(c[mt][nt], a[mt][0], a[mt][1], a[mt][2], a[mt][3],
                             b[nt][0], b[nt][1]);
        }
    }

    // ---------------- epilogue ----------------
    const int r = lane >> 2, cq = (lane & 3) * 2;
    #pragma unroll
    for (int mt = 0; mt < 4; mt++) {
        #pragma unroll
        for (int half_ = 0; half_ < 2; half_++) {
            int m = bm + wm + mt * 16 + r + half_ * 8;
            #pragma unroll
            for (int nt = 0; nt < 4; nt++) {
                int n = bn + wn + nt * 8 + cq;
                float v0 = c[mt][nt][half_ * 2 + 0];
                float v1 = c[mt][nt][half_ * 2 + 1];
                if (MODE == 0) {
                    int mat = n >> 10;
                    int hh = (n & 1023) >> 6, d = n & 63;
                    int bb = m >> 11, srow = m & (S_ - 1);
                    if (mat < 2) {
                        __half* dst = (mat == 0) ? q16 : k16;
                        *(__half2*)(dst + (((size_t)(bb * H_ + hh) * S_ + srow) << 6) + d)
                            = __floats2half2_rn(v0, v1);
                    } else {
                        __half* p = v16 + ((size_t)(bb * H_ + hh) * DH_ + d) * S_ + srow;
                        p[0]  = __float2half_rn(v0);
                        p[S_] = __float2half_rn(v1);
                    }
                } else if (MODE == 2) {
                    float2 bv = *(const float2*)(bias + n);
                    v0 = fmaxf(v0 + bv.x, 0.f);
                    v1 = fmaxf(v1 + bv.y, 0.f);
                    *(__half2*)(oh + (size_t)m * ldC + n) = __floats2half2_rn(v0, v1);
                } else {
                    size_t base = (size_t)m * ldC + n;
                    float2 bv = *(const float2*)(bias + n);
                    float2 rv = *(const float2*)(res + base);
                    *(float2*)(o0 + base) = make_float2(v0 + bv.x + rv.x,
                                                        v1 + bv.y + rv.y);
                }
            }
        }
    }
}

// ---------------- HMMA flash attention (causal) -------------------------------
// 128 queries x 64 keys per tile, 8 warps (16 q-rows each), fp16 in, fp16 out.
// Q,K: [B,H,S,DH] fp16; Vt: [B,H,DH,S] fp16; O: [B,S,E] fp16 (concat layout)
#define FLDS 72
#define FLASH_SMEM ((128 + 4*64) * FLDS * 2)   // 55296 B

__global__ void __launch_bounds__(256, 2) flash_kernel(
    const __half* __restrict__ Q, const __half* __restrict__ Kp,
    const __half* __restrict__ Vt, __half* __restrict__ O)
{
    extern __shared__ __half fsm[];
    const uint32_t qb = smem_u32(fsm);                 // Q [128][72]
    const uint32_t kb = qb + 128 * FLDS * 2;           // K [2][64][72]
    const uint32_t vb = kb + 2 * 64 * FLDS * 2;        // Vt [2][64][72]

    const int qt = (int)gridDim.x - 1 - (int)blockIdx.x;   // heavy tiles first
    const int h = blockIdx.y, b = blockIdx.z;
    const int t = threadIdx.x, wid = t >> 5, lane = t & 31;
    const int wm = wid * 16;

    const __half* Qg = Q  + (((size_t)(b * H_ + h)) * S_ + qt * 128) * DH_;
    const __half* Kg = Kp + ((size_t)(b * H_ + h)) * S_ * DH_;
    const __half* Vg = Vt + ((size_t)(b * H_ + h)) * DH_ * S_;

    auto load_kv = [&](int kt) {
        uint32_t st = (uint32_t)(kt & 1) * 64 * FLDS * 2;
        #pragma unroll
        for (int p = 0; p < 2; p++) {
            int idx = t + p * 256;
            int row = idx >> 3, ch = idx & 7;
            uint32_t off = (uint32_t)(row * FLDS + ch * 8) * 2;
            cp16(kb + st + off, Kg + (size_t)(kt * 64 + row) * DH_ + ch * 8);
            cp16(vb + st + off, Vg + (size_t)row * S_ + kt * 64 + ch * 8);
        }
    };

    // Q + KV(0) in one group
    #pragma unroll
    for (int p = 0; p < 4; p++) {
        int idx = t + p * 256;
        int row = idx >> 3, ch = idx & 7;
        cp16(qb + (uint32_t)(row * FLDS + ch * 8) * 2, Qg + (size_t)row * DH_ + ch * 8);
    }
    load_kv(0);
    CP_COMMIT();

    const float alpha = 0.125f * 1.44269504f;   // scale * log2(e)
    float m0 = -1e30f, m1 = -1e30f, l0 = 0.f, l1 = 0.f;
    float oc[8][4];
    #pragma unroll
    for (int j = 0; j < 8; j++)
        #pragma unroll
        for (int e = 0; e < 4; e++) oc[j][e] = 0.f;

    uint32_t qa[4][4];
    const int nkt = 2 * qt + 2;

    for (int kt = 0; kt < nkt; kt++) {
        if (kt + 1 < nkt) { load_kv(kt + 1); CP_COMMIT(); CP_WAIT(1); }
        else              { CP_WAIT(0); }
        __syncthreads();

        if (kt == 0) {   // Q fragments, loaded once
            #pragma unroll
            for (int ks = 0; ks < 4; ks++) {
                uint32_t addr = qb + (uint32_t)(((wm + (lane & 15)) * FLDS
                                   + ks * 16 + (lane >> 4) * 8) * 2);
                ldm_x4(qa[ks][0], qa[ks][1], qa[ks][2], qa[ks][3], addr);
            }
        }

        // ---- S = Q K^T ----
        float sc[8][4];
        #pragma unroll
        for (int j = 0; j < 8; j++)
            #pragma unroll
            for (int e = 0; e < 4; e++) sc[j][e] = 0.f;

        uint32_t kbs = kb + (uint32_t)(kt & 1) * 64 * FLDS * 2;
        #pragma unroll
        for (int ks = 0; ks < 4; ks++) {
            uint32_t bfr[8][2];
            #pragma unroll
            for (int np = 0; np < 4; np++) {
                int nrow = np * 16 + (lane & 7) + ((lane >> 4) << 3);
                int ncol = ks * 16 + (((lane >> 3) & 1) << 3);
                uint32_t r0, r1, r2, r3;
                ldm_x4(r0, r1, r2, r3, kbs + (uint32_t)((nrow * FLDS + ncol) * 2));
                bfr[2*np][0] = r0; bfr[2*np][1] = r1;
                bfr[2*np+1][0] = r2; bfr[2*np+1][1] = r3;
            }
            #pragma unroll
            for (int j = 0; j < 8; j++)
                mma16816(sc[j], qa[ks][0], qa[ks][1], qa[ks][2], qa[ks][3],
                         bfr[j][0], bfr[j][1]);
        }

        // ---- causal mask (only diagonal key tiles) ----
        if (kt >= 2 * qt) {
            int row0 = qt * 128 + wm + (lane >> 2);
            int colb = kt * 64 + 2 * (lane & 3);
            #pragma unroll
            for (int j = 0; j < 8; j++) {
                #pragma unroll
                for (int cc = 0; cc < 2; cc++) {
                    int col = colb + j * 8 + cc;
                    if (col > row0)     sc[j][cc]     = -1e30f;
                    if (col > row0 + 8) sc[j][2 + cc] = -1e30f;
                }
            }
        }

        // ---- online softmax ----
        float mx0 = -1e30f, mx1 = -1e30f;
        #pragma unroll
        for (int j = 0; j < 8; j++) {
            mx0 = fmaxf(mx0, fmaxf(sc[j][0], sc[j][1]));
            mx1 = fmaxf(mx1, fmaxf(sc[j][2], sc[j][3]));
        }
        mx0 = fmaxf(mx0, __shfl_xor_sync(0xffffffffu, mx0, 1));
        mx0 = fmaxf(mx0, __shfl_xor_sync(0xffffffffu, mx0, 2));
        mx1 = fmaxf(mx1, __shfl_xor_sync(0xffffffffu, mx1, 1));
        mx1 = fmaxf(mx1, __shfl_xor_sync(0xffffffffu, mx1, 2));
        float nm0 = fmaxf(m0, mx0), nm1 = fmaxf(m1, mx1);
        float c0 = fexp2((m0 - nm0) * alpha);
        float c1 = fexp2((m1 - nm1) * alpha);
        m0 = nm0; m1 = nm1;
        float ma0 = m0 * alpha, ma1 = m1 * alpha;

        float rs0 = 0.f, rs1 = 0.f;
        uint32_t pa[4][4];   // P fragments: kstep ks <- tiles 2ks, 2ks+1
        #pragma unroll
        for (int j = 0; j < 8; j++) {
            float p0 = fexp2(fmaf(sc[j][0], alpha, -ma0));
            float p1 = fexp2(fmaf(sc[j][1], alpha, -ma0));
            float p2 = fexp2(fmaf(sc[j][2], alpha, -ma1));
            float p3 = fexp2(fmaf(sc[j][3], alpha, -ma1));
            rs0 += p0 + p1; rs1 += p2 + p3;
            int ks = j >> 1, hi = (j & 1) << 1;
            pa[ks][hi]     = h2_as_u32(__floats2half2_rn(p0, p1));
            pa[ks][hi + 1] = h2_as_u32(__floats2half2_rn(p2, p3));
        }
        rs0 += __shfl_xor_sync(0xffffffffu, rs0, 1);
        rs0 += __shfl_xor_sync(0xffffffffu, rs0, 2);
        rs1 += __shfl_xor_sync(0xffffffffu, rs1, 1);
        rs1 += __shfl_xor_sync(0xffffffffu, rs1, 2);
        l0 = l0 * c0 + rs0;
        l1 = l1 * c1 + rs1;
        #pragma unroll
        for (int j = 0; j < 8; j++) {
            oc[j][0] *= c0; oc[j][1] *= c0;
            oc[j][2] *= c1; oc[j][3] *= c1;
        }

        // ---- O += P V ----
        uint32_t vbs = vb + (uint32_t)(kt & 1) * 64 * FLDS * 2;
        #pragma unroll
        for (int ks = 0; ks < 4; ks++) {
            uint32_t vfr[8][2];
            #pragma unroll
            for (int np = 0; np < 4; np++) {
                int nrow = np * 16 + (lane & 7) + ((lane >> 4) << 3);
                int ncol = ks * 16 + (((lane >> 3) & 1) << 3);
                uint32_t r0, r1, r2, r3;
                ldm_x4(r0, r1, r2, r3, vbs + (uint32_t)((nrow * FLDS + ncol) * 2));
                vfr[2*np][0] = r0; vfr[2*np][1] = r1;
                vfr[2*np+1][0] = r2; vfr[2*np+1][1] = r3;
            }
            #pragma unroll
            for (int j = 0; j < 8; j++)
                mma16816(oc[j], pa[ks][0], pa[ks][1], pa[ks][2], pa[ks][3],
                         vfr[j][0], vfr[j][1]);
        }
        __syncthreads();
    }

    // ---- write O (concat layout, fp16) ----
    float i0 = 1.0f / l0, i1 = 1.0f / l1;
    int row0 = qt * 128 + wm + (lane >> 2);
    size_t base0 = ((size_t)b * S_ + row0) * E_ + h * 64 + 2 * (lane & 3);
    size_t base1 = base0 + (size_t)8 * E_;
    #pragma unroll
    for (int j = 0; j < 8; j++) {
        *(__half2*)(O + base0 + j * 8) = __floats2half2_rn(oc[j][0] * i0, oc[j][1] * i0);
        *(__half2*)(O + base1 + j * 8) = __floats2half2_rn(oc[j][2] * i1, oc[j][3] * i1);
    }
}

// ---------------- host launcher ----------------
extern "C" void kernel_launch(void* const* d_in, const int* in_sizes, int n_in,
                              void* d_out, int out_size)
{
    const float* x   = (const float*)d_in[0];
    const float* Wq  = (const float*)d_in[1];
    const float* Wk  = (const float*)d_in[2];
    const float* Wv  = (const float*)d_in[3];
    const float* Wo  = (const float*)d_in[4];
    const float* bo  = (const float*)d_in[5];
    const float* W1  = (const float*)d_in[6];
    const float* b1  = (const float*)d_in[7];
    const float* W2  = (const float*)d_in[8];
    const float* b2  = (const float*)d_in[9];
    const float* g1  = (const float*)d_in[10];
    const float* be1 = (const float*)d_in[11];
    const float* g2  = (const float*)d_in[12];
    const float* be2 = (const float*)d_in[13];
    float* out = (float*)d_out;

    void *nx, *wqkv_hi, *wqkv_lo, *wo_hi, *wo_lo, *w1_hi, *w1_lo, *w2_hi, *w2_lo,
         *q, *k, *vt, *attn, *x1, *nx2, *ffn;
    cudaGetSymbolAddress(&nx, g_nx);
    cudaGetSymbolAddress(&wqkv_hi, g_wqkv_hi); cudaGetSymbolAddress(&wqkv_lo, g_wqkv_lo);
    cudaGetSymbolAddress(&wo_hi, g_wo_hi);   cudaGetSymbolAddress(&wo_lo, g_wo_lo);
    cudaGetSymbolAddress(&w1_hi, g_w1_hi);   cudaGetSymbolAddress(&w1_lo, g_w1_lo);
    cudaGetSymbolAddress(&w2_hi, g_w2_hi);   cudaGetSymbolAddress(&w2_lo, g_w2_lo);
    cudaGetSymbolAddress(&q, g_q); cudaGetSymbolAddress(&k, g_k);
    cudaGetSymbolAddress(&vt, g_vt);
    cudaGetSymbolAddress(&attn, g_attn);
    cudaGetSymbolAddress(&x1, g_x1);
    cudaGetSymbolAddress(&nx2, g_nx2);
    cudaGetSymbolAddress(&ffn, g_ffn);

    cudaFuncSetAttribute(gemm_mma_kernel<0>, cudaFuncAttributeMaxDynamicSharedMemorySize, GEMM_SMEM);
    cudaFuncSetAttribute(gemm_mma_kernel<1>, cudaFuncAttributeMaxDynamicSharedMemorySize, GEMM_SMEM);
    cudaFuncSetAttribute(gemm_mma_kernel<2>, cudaFuncAttributeMaxDynamicSharedMemorySize, GEMM_SMEM);
    cudaFuncSetAttribute(gemm_mma_kernel<3>, cudaFuncAttributeMaxDynamicSharedMemorySize, GEMM_SMEM);
    cudaFuncSetAttribute(flash_kernel, cudaFuncAttributeMaxDynamicSharedMemorySize, FLASH_SMEM);

    // 1. weight transpose+split (fp16 hi/lo)
    wqkv_split_kernel<<<dim3(E_/32, NQKV/32), 256>>>(Wq, Wk, Wv,
        (__half*)wqkv_hi, (__half*)wqkv_lo);
    wt_split_kernel<<<dim3(E_/32, E_/32), 256>>>(Wo, E_, E_,
        (__half*)wo_hi, (__half*)wo_lo);
    wt_split_kernel<<<dim3(E_/32, FF_/32), 256>>>(W1, E_, FF_,
        (__half*)w1_hi, (__half*)w1_lo);
    wt_split_kernel<<<dim3(FF_/32, E_/32), 256>>>(W2, FF_, E_,
        (__half*)w2_hi, (__half*)w2_lo);
    // 2. LN1 -> fp16
    ln_fp16_kernel<<<TOK, 256>>>(x, g1, be1, (__half*)nx);
    // 3. fused QKV GEMM (N=3072) -> q,k fp16 [B,H,S,DH]; v fp16 [B,H,DH,S]
    gemm_mma_kernel<0><<<dim3(NQKV/128, TOK/128), 256, GEMM_SMEM>>>(
        (__half*)nx, (__half*)wqkv_hi, (__half*)wqkv_lo,
        nullptr, nullptr, nullptr, nullptr,
        (__half*)q, (__half*)k, (__half*)vt, E_, 0);
    // 4. HMMA flash attention -> attn fp16
    flash_kernel<<<dim3(S_/128, H_, B_), 256, FLASH_SMEM>>>(
        (__half*)q, (__half*)k, (__half*)vt, (__half*)attn);
    // 5. output projection + residual -> x1 fp32
    gemm_mma_kernel<1><<<dim3(E_/128, TOK/128), 256, GEMM_SMEM>>>(
        (__half*)attn, (__half*)wo_hi, (__half*)wo_lo,
        bo, x, (float*)x1, nullptr, nullptr, nullptr, nullptr, E_, E_);
    // 6. LN2 -> fp16
    ln_fp16_kernel<<<TOK, 256>>>((float*)x1, g2, be2, (__half*)nx2);
    // 7. FFN1: relu(+b1) -> ffn fp16
    gemm_mma_kernel<2><<<dim3(FF_/128, TOK/128), 256, GEMM_SMEM>>>(
        (__half*)nx2, (__half*)w1_hi, (__half*)w1_lo,
        b1, nullptr, nullptr, (__half*)ffn, nullptr, nullptr, nullptr, E_, FF_);
    // 8. FFN2: +b2 +x1 -> out
    gemm_mma_kernel<3><<<dim3(E_/128, TOK/128), 256, GEMM_SMEM>>>(
        (__half*)ffn, (__half*)w2_hi, (__half*)w2_lo,
        b2, (float*)x1, out, nullptr, nullptr, nullptr, nullptr, FF_, E_);
}

// round 9
// speedup vs baseline: 3.7472x; 1.5559x over previous
#include <cuda_runtime.h>
#include <cuda_fp16.h>
#include <cstdint>

#define B_   2
#define S_   2048
#define E_   1024
#define H_   16
#define DH_  64
#define FF_  4096
#define TOK  (B_*S_)   // 4096
#define NQKV 3072

// ---------------- scratch (no allocs allowed) ----------------
__device__ __half g_nx   [TOK*(size_t)E_];
__device__ __half g_wqkv [(size_t)NQKV*E_];
__device__ __half g_wo   [(size_t)E_*E_];
__device__ __half g_w1   [(size_t)FF_*E_];
__device__ __half g_w2   [(size_t)E_*FF_];
__device__ __half g_q [(size_t)B_*H_*S_*DH_];
__device__ __half g_k [(size_t)B_*H_*S_*DH_];
__device__ __half g_vt[(size_t)B_*H_*DH_*S_];   // V transposed: [B,H,DH,S]
__device__ __half g_attn[TOK*(size_t)E_];
__device__ float g_x1[TOK*(size_t)E_];
__device__ __half g_nx2 [TOK*(size_t)E_];
__device__ __half g_ffn [TOK*(size_t)FF_];

// ---------------- PTX helpers (base-target-safe: sm_80 features) -------------
__device__ __forceinline__ uint32_t smem_u32(const void* p) {
    uint32_t a;
    asm("{ .reg .u64 t; cvta.to.shared.u64 t, %1; cvt.u32.u64 %0, t; }" : "=r"(a) : "l"(p));
    return a;
}
__device__ __forceinline__ uint32_t h2_as_u32(__half2 h) {
    union { __half2 h2; uint32_t u; } cvt;
    cvt.h2 = h;
    return cvt.u;
}
__device__ __forceinline__ void cp16(uint32_t s, const void* g) {
    asm volatile("cp.async.cg.shared.global [%0], [%1], 16;" :: "r"(s), "l"(g));
}
#define CP_COMMIT() asm volatile("cp.async.commit_group;" ::: "memory")
#define CP_WAIT(n)  asm volatile("cp.async.wait_group %0;" :: "n"(n) : "memory")

__device__ __forceinline__ void ldm_x4(uint32_t& r0, uint32_t& r1, uint32_t& r2,
                                       uint32_t& r3, uint32_t a) {
    asm volatile("ldmatrix.sync.aligned.m8n8.x4.shared.b16 {%0,%1,%2,%3}, [%4];"
                 : "=r"(r0), "=r"(r1), "=r"(r2), "=r"(r3) : "r"(a));
}
__device__ __forceinline__ void mma16816(float* c, uint32_t a0, uint32_t a1,
                                         uint32_t a2, uint32_t a3,
                                         uint32_t b0, uint32_t b1) {
    asm volatile(
        "mma.sync.aligned.m16n8k16.row.col.f32.f16.f16.f32 "
        "{%0,%1,%2,%3},{%4,%5,%6,%7},{%8,%9},{%0,%1,%2,%3};"
        : "+f"(c[0]), "+f"(c[1]), "+f"(c[2]), "+f"(c[3])
        : "r"(a0), "r"(a1), "r"(a2), "r"(a3), "r"(b0), "r"(b1));
}

// fast 2^x on the FMA pipe (no MUFU). x clamped to [-125, ~0]. rel err ~1e-7.
__device__ __forceinline__ float fexp2(float x) {
    x = fmaxf(x, -125.0f);
    float t = x + 12582912.0f;              // 1.5*2^23: round-to-int in mantissa
    int n = __float_as_int(t) - 0x4B400000; // integer part
    float f = x - (t - 12582912.0f);        // frac in [-0.5, 0.5]
    float p =              1.5403530e-4f;
    p = fmaf(p, f, 1.3333558e-3f);
    p = fmaf(p, f, 9.6181291e-3f);
    p = fmaf(p, f, 5.5504109e-2f);
    p = fmaf(p, f, 2.4022651e-1f);
    p = fmaf(p, f, 6.9314718e-1f);
    p = fmaf(p, f, 1.0f);
    return p * __int_as_float((n + 127) << 23);
}

// ---------------- LayerNorm -> fp16: one block per token ---------------------
__global__ void __launch_bounds__(256) ln_fp16_kernel(
    const float* __restrict__ x, const float* __restrict__ g,
    const float* __restrict__ bta, __half* __restrict__ o)
{
    __shared__ float sh1[8], sh2[8];
    int tok = blockIdx.x;
    int t = threadIdx.x;
    const float4* xr = (const float4*)(x + (size_t)tok * E_);
    float4 v = xr[t];
    float sum = v.x + v.y + v.z + v.w;
    float sq  = v.x*v.x + v.y*v.y + v.z*v.z + v.w*v.w;
    #pragma unroll
    for (int o2 = 16; o2 > 0; o2 >>= 1) {
        sum += __shfl_xor_sync(0xffffffffu, sum, o2);
        sq  += __shfl_xor_sync(0xffffffffu, sq,  o2);
    }
    if ((t & 31) == 0) { sh1[t >> 5] = sum; sh2[t >> 5] = sq; }
    __syncthreads();
    if (t < 32) {
        sum = (t < 8) ? sh1[t] : 0.f;
        sq  = (t < 8) ? sh2[t] : 0.f;
        #pragma unroll
        for (int o2 = 4; o2 > 0; o2 >>= 1) {
            sum += __shfl_xor_sync(0xffffffffu, sum, o2);
            sq  += __shfl_xor_sync(0xffffffffu, sq,  o2);
        }
        if (t == 0) { sh1[0] = sum; sh2[0] = sq; }
    }
    __syncthreads();
    sum = sh1[0]; sq = sh2[0];
    float mu  = sum * (1.0f / E_);
    float var = sq * (1.0f / E_) - mu * mu;
    float rs  = rsqrtf(var + 1e-5f);
    float4 gv = ((const float4*)g)[t];
    float4 bv = ((const float4*)bta)[t];
    float a0 = (v.x - mu) * rs * gv.x + bv.x;
    float a1 = (v.y - mu) * rs * gv.y + bv.y;
    float a2 = (v.z - mu) * rs * gv.z + bv.z;
    float a3 = (v.w - mu) * rs * gv.w + bv.w;
    size_t base = (size_t)tok * E_ + t * 4;
    *(__half2*)(o + base)     = __floats2half2_rn(a0, a1);
    *(__half2*)(o + base + 2) = __floats2half2_rn(a2, a3);
}

// ---------------- weight transpose -> fp16: W[K,N] -> Wt[N,K] ----------------
__global__ void __launch_bounds__(256) wt_fp16_kernel(
    const float* __restrict__ W, int K, int N, __half* __restrict__ o)
{
    __shared__ float t[32][33];
    int k0 = blockIdx.x * 32, n0 = blockIdx.y * 32;
    int tx = threadIdx.x & 31, ty = threadIdx.x >> 5;
    #pragma unroll
    for (int r = 0; r < 4; r++)
        t[ty + 8*r][tx] = W[(size_t)(k0 + ty + 8*r) * N + n0 + tx];
    __syncthreads();
    #pragma unroll
    for (int r = 0; r < 4; r++)
        o[(size_t)(n0 + ty + 8*r) * K + k0 + tx] = __float2half_rn(t[tx][ty + 8*r]);
}

// QKV weights [H,E,DH] x3 -> fused Wt[3072, E] fp16
__global__ void __launch_bounds__(256) wqkv_fp16_kernel(
    const float* __restrict__ Wq, const float* __restrict__ Wk,
    const float* __restrict__ Wv, __half* __restrict__ o)
{
    __shared__ float t[32][33];
    int e0 = blockIdx.x * 32, n0 = blockIdx.y * 32;
    const float* Wm = (n0 < 1024) ? Wq : (n0 < 2048) ? Wk : Wv;
    int nn = n0 & 1023;
    int h = nn >> 6, d0 = nn & 63;
    int tx = threadIdx.x & 31, ty = threadIdx.x >> 5;
    #pragma unroll
    for (int r = 0; r < 4; r++)
        t[ty + 8*r][tx] = Wm[((size_t)h * E_ + e0 + ty + 8*r) * DH_ + d0 + tx];
    __syncthreads();
    #pragma unroll
    for (int r = 0; r < 4; r++)
        o[(size_t)(n0 + ty + 8*r) * E_ + e0 + tx] = __float2half_rn(t[tx][ty + 8*r]);
}

// ---------------- HMMA GEMM: C[M,N] = A[M,K]*Bt[N,K]^T, plain fp16 -----------
// MODE 0: QKV scatter: q,k fp16 [B,H,S,DH]; v fp16 transposed [B,H,DH,S]
// MODE 1/3: + bias + res -> o0 fp32
// MODE 2: relu(+bias) -> oh fp16
#define BK     32
#define LDS    40
#define AELEMS (128 * LDS)
#define ABYTES (AELEMS * 2)            // 10240
#define STG_BYTES (2 * ABYTES)
#define GEMM_SMEM (4 * STG_BYTES)      // 81920 -> 2 CTA/SM

template<int MODE>
__global__ void __launch_bounds__(256, 2) gemm_mma_kernel(
    const __half* __restrict__ A, const __half* __restrict__ Bt,
    const float* __restrict__ bias, const float* __restrict__ res,
    float* __restrict__ o0, __half* __restrict__ oh,
    __half* __restrict__ q16, __half* __restrict__ k16, __half* __restrict__ v16,
    int K, int ldC)
{
    extern __shared__ __half smbuf[];
    const uint32_t sbase = smem_u32(smbuf);
    const int NIT = K / BK;
    const int t = threadIdx.x;
    const int wid = t >> 5, lane = t & 31;
    const int bm = blockIdx.y * 128, bn = blockIdx.x * 128;
    const int wm = (wid & 1) * 64, wn = (wid >> 1) * 32;

    const __half* Abase = A  + (size_t)bm * K;
    const __half* Bbase = Bt + (size_t)bn * K;

    auto load_stage = [&](int st, int i) {
        uint32_t sa = sbase + st * STG_BYTES;
        int kc = i * BK;
        #pragma unroll
        for (int p = 0; p < 2; p++) {
            int idx = t + p * 256;
            int row = idx >> 2, ch = idx & 3;
            uint32_t off = (uint32_t)(row * LDS + ch * 8) * 2;
            cp16(sa + off,          Abase + (size_t)row * K + kc + ch * 8);
            cp16(sa + ABYTES + off, Bbase + (size_t)row * K + kc + ch * 8);
        }
    };

    #pragma unroll
    for (int s = 0; s < 3; s++) { load_stage(s, s); CP_COMMIT(); }

    float c[4][4][4];
    #pragma unroll
    for (int mt = 0; mt < 4; mt++)
        #pragma unroll
        for (int nt = 0; nt < 4; nt++)
            #pragma unroll
            for (int e = 0; e < 4; e++) c[mt][nt][e] = 0.f;

    for (int i = 0; i < NIT; i++) {
        CP_WAIT(2);
        __syncthreads();
        if (i + 3 < NIT) load_stage((i + 3) & 3, i + 3);
        CP_COMMIT();

        uint32_t sa = sbase + (i & 3) * STG_BYTES;
        uint32_t sb = sa + ABYTES;
        #pragma unroll
        for (int ks = 0; ks < 2; ks++) {
            uint32_t a[4][4];
            #pragma unroll
            for (int mt = 0; mt < 4; mt++) {
                uint32_t addr = sa + (uint32_t)(((wm + mt*16 + (lane & 15)) * LDS
                                  + ks*16 + (lane >> 4) * 8) * 2);
                ldm_x4(a[mt][0], a[mt][1], a[mt][2], a[mt][3], addr);
            }
            uint32_t b[4][2];
            #pragma unroll
            for (int np = 0; np < 2; np++) {
                int nrow = wn + np*16 + (lane & 7) + ((lane >> 4) << 3);
                int ncol = ks*16 + (((lane >> 3) & 1) << 3);
                uint32_t addr = sb + (uint32_t)((nrow * LDS + ncol) * 2);
                uint32_t r0, r1, r2, r3;
                ldm_x4(r0, r1, r2, r3, addr);
                b[2*np][0] = r0; b[2*np][1] = r1;
                b[2*np+1][0] = r2; b[2*np+1][1] = r3;
            }
            #pragma unroll
            for (int mt = 0; mt < 4; mt++)
                #pragma unroll
                for (int nt = 0; nt < 4; nt++)
                    mma16816(c[mt][nt], a[mt][0], a[mt][1], a[mt][2], a[mt][3],
                             b[nt][0], b[nt][1]);
        }
    }

    // ---------------- epilogue ----------------
    const int r = lane >> 2, cq = (lane & 3) * 2;
    #pragma unroll
    for (int mt = 0; mt < 4; mt++) {
        #pragma unroll
        for (int half_ = 0; half_ < 2; half_++) {
            int m = bm + wm + mt * 16 + r + half_ * 8;
            #pragma unroll
            for (int nt = 0; nt < 4; nt++) {
                int n = bn + wn + nt * 8 + cq;
                float v0 = c[mt][nt][half_ * 2 + 0];
                float v1 = c[mt][nt][half_ * 2 + 1];
                if (MODE == 0) {
                    int mat = n >> 10;
                    int hh = (n & 1023) >> 6, d = n & 63;
                    int bb = m >> 11, srow = m & (S_ - 1);
                    if (mat < 2) {
                        __half* dst = (mat == 0) ? q16 : k16;
                        *(__half2*)(dst + (((size_t)(bb * H_ + hh) * S_ + srow) << 6) + d)
                            = __floats2half2_rn(v0, v1);
                    } else {
                        __half* p = v16 + ((size_t)(bb * H_ + hh) * DH_ + d) * S_ + srow;
                        p[0]  = __float2half_rn(v0);
                        p[S_] = __float2half_rn(v1);
                    }
                } else if (MODE == 2) {
                    float2 bv = *(const float2*)(bias + n);
                    v0 = fmaxf(v0 + bv.x, 0.f);
                    v1 = fmaxf(v1 + bv.y, 0.f);
                    *(__half2*)(oh + (size_t)m * ldC + n) = __floats2half2_rn(v0, v1);
                } else {
                    size_t base = (size_t)m * ldC + n;
                    float2 bv = *(const float2*)(bias + n);
                    float2 rv = *(const float2*)(res + base);
                    *(float2*)(o0 + base) = make_float2(v0 + bv.x + rv.x,
                                                        v1 + bv.y + rv.y);
                }
            }
        }
    }
}

// ---------------- HMMA flash attention (causal) -------------------------------
// 128 queries x 64 keys per tile, 8 warps (16 q-rows each), fp16 in, fp16 out.
// Q,K: [B,H,S,DH] fp16; Vt: [B,H,DH,S] fp16; O: [B,S,E] fp16 (concat layout)
#define FLDS 72
#define FLASH_SMEM ((128 + 4*64) * FLDS * 2)   // 55296 B

__global__ void __launch_bounds__(256, 2) flash_kernel(
    const __half* __restrict__ Q, const __half* __restrict__ Kp,
    const __half* __restrict__ Vt, __half* __restrict__ O)
{
    extern __shared__ __half fsm[];
    const uint32_t qb = smem_u32(fsm);                 // Q [128][72]
    const uint32_t kb = qb + 128 * FLDS * 2;           // K [2][64][72]
    const uint32_t vb = kb + 2 * 64 * FLDS * 2;        // Vt [2][64][72]

    const int qt = (int)gridDim.x - 1 - (int)blockIdx.x;   // heavy tiles first
    const int h = blockIdx.y, b = blockIdx.z;
    const int t = threadIdx.x, wid = t >> 5, lane = t & 31;
    const int wm = wid * 16;

    const __half* Qg = Q  + (((size_t)(b * H_ + h)) * S_ + qt * 128) * DH_;
    const __half* Kg = Kp + ((size_t)(b * H_ + h)) * S_ * DH_;
    const __half* Vg = Vt + ((size_t)(b * H_ + h)) * DH_ * S_;

    auto load_kv = [&](int kt) {
        uint32_t st = (uint32_t)(kt & 1) * 64 * FLDS * 2;
        #pragma unroll
        for (int p = 0; p < 2; p++) {
            int idx = t + p * 256;
            int row = idx >> 3, ch = idx & 7;
            uint32_t off = (uint32_t)(row * FLDS + ch * 8) * 2;
            cp16(kb + st + off, Kg + (size_t)(kt * 64 + row) * DH_ + ch * 8);
            cp16(vb + st + off, Vg + (size_t)row * S_ + kt * 64 + ch * 8);
        }
    };

    // Q + KV(0) in one group
    #pragma unroll
    for (int p = 0; p < 4; p++) {
        int idx = t + p * 256;
        int row = idx >> 3, ch = idx & 7;
        cp16(qb + (uint32_t)(row * FLDS + ch * 8) * 2, Qg + (size_t)row * DH_ + ch * 8);
    }
    load_kv(0);
    CP_COMMIT();

    const float alpha = 0.125f * 1.44269504f;   // scale * log2(e)
    float m0 = -1e30f, m1 = -1e30f, l0 = 0.f, l1 = 0.f;
    float oc[8][4];
    #pragma unroll
    for (int j = 0; j < 8; j++)
        #pragma unroll
        for (int e = 0; e < 4; e++) oc[j][e] = 0.f;

    uint32_t qa[4][4];
    const int nkt = 2 * qt + 2;

    for (int kt = 0; kt < nkt; kt++) {
        if (kt + 1 < nkt) { load_kv(kt + 1); CP_COMMIT(); CP_WAIT(1); }
        else              { CP_WAIT(0); }
        __syncthreads();

        if (kt == 0) {   // Q fragments, loaded once
            #pragma unroll
            for (int ks = 0; ks < 4; ks++) {
                uint32_t addr = qb + (uint32_t)(((wm + (lane & 15)) * FLDS
                                   + ks * 16 + (lane >> 4) * 8) * 2);
                ldm_x4(qa[ks][0], qa[ks][1], qa[ks][2], qa[ks][3], addr);
            }
        }

        // ---- S = Q K^T ----
        float sc[8][4];
        #pragma unroll
        for (int j = 0; j < 8; j++)
            #pragma unroll
            for (int e = 0; e < 4; e++) sc[j][e] = 0.f;

        uint32_t kbs = kb + (uint32_t)(kt & 1) * 64 * FLDS * 2;
        #pragma unroll
        for (int ks = 0; ks < 4; ks++) {
            uint32_t bfr[8][2];
            #pragma unroll
            for (int np = 0; np < 4; np++) {
                int nrow = np * 16 + (lane & 7) + ((lane >> 4) << 3);
                int ncol = ks * 16 + (((lane >> 3) & 1) << 3);
                uint32_t r0, r1, r2, r3;
                ldm_x4(r0, r1, r2, r3, kbs + (uint32_t)((nrow * FLDS + ncol) * 2));
                bfr[2*np][0] = r0; bfr[2*np][1] = r1;
                bfr[2*np+1][0] = r2; bfr[2*np+1][1] = r3;
            }
            #pragma unroll
            for (int j = 0; j < 8; j++)
                mma16816(sc[j], qa[ks][0], qa[ks][1], qa[ks][2], qa[ks][3],
                         bfr[j][0], bfr[j][1]);
        }

        // ---- causal mask (only diagonal key tiles) ----
        if (kt >= 2 * qt) {
            int row0 = qt * 128 + wm + (lane >> 2);
            int colb = kt * 64 + 2 * (lane & 3);
            #pragma unroll
            for (int j = 0; j < 8; j++) {
                #pragma unroll
                for (int cc = 0; cc < 2; cc++) {
                    int col = colb + j * 8 + cc;
                    if (col > row0)     sc[j][cc]     = -1e30f;
                    if (col > row0 + 8) sc[j][2 + cc] = -1e30f;
                }
            }
        }

        // ---- online softmax ----
        float mx0 = -1e30f, mx1 = -1e30f;
        #pragma unroll
        for (int j = 0; j < 8; j++) {
            mx0 = fmaxf(mx0, fmaxf(sc[j][0], sc[j][1]));
            mx1 = fmaxf(mx1, fmaxf(sc[j][2], sc[j][3]));
        }
        mx0 = fmaxf(mx0, __shfl_xor_sync(0xffffffffu, mx0, 1));
        mx0 = fmaxf(mx0, __shfl_xor_sync(0xffffffffu, mx0, 2));
        mx1 = fmaxf(mx1, __shfl_xor_sync(0xffffffffu, mx1, 1));
        mx1 = fmaxf(mx1, __shfl_xor_sync(0xffffffffu, mx1, 2));
        float nm0 = fmaxf(m0, mx0), nm1 = fmaxf(m1, mx1);
        float c0 = fexp2((m0 - nm0) * alpha);
        float c1 = fexp2((m1 - nm1) * alpha);
        m0 = nm0; m1 = nm1;
        float ma0 = m0 * alpha, ma1 = m1 * alpha;

        float rs0 = 0.f, rs1 = 0.f;
        uint32_t pa[4][4];   // P fragments: kstep ks <- tiles 2ks, 2ks+1
        #pragma unroll
        for (int j = 0; j < 8; j++) {
            float p0 = fexp2(fmaf(sc[j][0], alpha, -ma0));
            float p1 = fexp2(fmaf(sc[j][1], alpha, -ma0));
            float p2 = fexp2(fmaf(sc[j][2], alpha, -ma1));
            float p3 = fexp2(fmaf(sc[j][3], alpha, -ma1));
            rs0 += p0 + p1; rs1 += p2 + p3;
            int ks = j >> 1, hi = (j & 1) << 1;
            pa[ks][hi]     = h2_as_u32(__floats2half2_rn(p0, p1));
            pa[ks][hi + 1] = h2_as_u32(__floats2half2_rn(p2, p3));
        }
        rs0 += __shfl_xor_sync(0xffffffffu, rs0, 1);
        rs0 += __shfl_xor_sync(0xffffffffu, rs0, 2);
        rs1 += __shfl_xor_sync(0xffffffffu, rs1, 1);
        rs1 += __shfl_xor_sync(0xffffffffu, rs1, 2);
        l0 = l0 * c0 + rs0;
        l1 = l1 * c1 + rs1;
        #pragma unroll
        for (int j = 0; j < 8; j++) {
            oc[j][0] *= c0; oc[j][1] *= c0;
            oc[j][2] *= c1; oc[j][3] *= c1;
        }

        // ---- O += P V ----
        uint32_t vbs = vb + (uint32_t)(kt & 1) * 64 * FLDS * 2;
        #pragma unroll
        for (int ks = 0; ks < 4; ks++) {
            uint32_t vfr[8][2];
            #pragma unroll
            for (int np = 0; np < 4; np++) {
                int nrow = np * 16 + (lane & 7) + ((lane >> 4) << 3);
                int ncol = ks * 16 + (((lane >> 3) & 1) << 3);
                uint32_t r0, r1, r2, r3;
                ldm_x4(r0, r1, r2, r3, vbs + (uint32_t)((nrow * FLDS + ncol) * 2));
                vfr[2*np][0] = r0; vfr[2*np][1] = r1;
                vfr[2*np+1][0] = r2; vfr[2*np+1][1] = r3;
            }
            #pragma unroll
            for (int j = 0; j < 8; j++)
                mma16816(oc[j], pa[ks][0], pa[ks][1], pa[ks][2], pa[ks][3],
                         vfr[j][0], vfr[j][1]);
        }
        __syncthreads();
    }

    // ---- write O (concat layout, fp16) ----
    float i0 = 1.0f / l0, i1 = 1.0f / l1;
    int row0 = qt * 128 + wm + (lane >> 2);
    size_t base0 = ((size_t)b * S_ + row0) * E_ + h * 64 + 2 * (lane & 3);
    size_t base1 = base0 + (size_t)8 * E_;
    #pragma unroll
    for (int j = 0; j < 8; j++) {
        *(__half2*)(O + base0 + j * 8) = __floats2half2_rn(oc[j][0] * i0, oc[j][1] * i0);
        *(__half2*)(O + base1 + j * 8) = __floats2half2_rn(oc[j][2] * i1, oc[j][3] * i1);
    }
}

// ---------------- host launcher ----------------
extern "C" void kernel_launch(void* const* d_in, const int* in_sizes, int n_in,
                              void* d_out, int out_size)
{
    const float* x   = (const float*)d_in[0];
    const float* Wq  = (const float*)d_in[1];
    const float* Wk  = (const float*)d_in[2];
    const float* Wv  = (const float*)d_in[3];
    const float* Wo  = (const float*)d_in[4];
    const float* bo  = (const float*)d_in[5];
    const float* W1  = (const float*)d_in[6];
    const float* b1  = (const float*)d_in[7];
    const float* W2  = (const float*)d_in[8];
    const float* b2  = (const float*)d_in[9];
    const float* g1  = (const float*)d_in[10];
    const float* be1 = (const float*)d_in[11];
    const float* g2  = (const float*)d_in[12];
    const float* be2 = (const float*)d_in[13];
    float* out = (float*)d_out;

    void *nx, *wqkv, *wo, *w1, *w2, *q, *k, *vt, *attn, *x1, *nx2, *ffn;
    cudaGetSymbolAddress(&nx, g_nx);
    cudaGetSymbolAddress(&wqkv, g_wqkv);
    cudaGetSymbolAddress(&wo, g_wo);
    cudaGetSymbolAddress(&w1, g_w1);
    cudaGetSymbolAddress(&w2, g_w2);
    cudaGetSymbolAddress(&q, g_q); cudaGetSymbolAddress(&k, g_k);
    cudaGetSymbolAddress(&vt, g_vt);
    cudaGetSymbolAddress(&attn, g_attn);
    cudaGetSymbolAddress(&x1, g_x1);
    cudaGetSymbolAddress(&nx2, g_nx2);
    cudaGetSymbolAddress(&ffn, g_ffn);

    cudaFuncSetAttribute(gemm_mma_kernel<0>, cudaFuncAttributeMaxDynamicSharedMemorySize, GEMM_SMEM);
    cudaFuncSetAttribute(gemm_mma_kernel<1>, cudaFuncAttributeMaxDynamicSharedMemorySize, GEMM_SMEM);
    cudaFuncSetAttribute(gemm_mma_kernel<2>, cudaFuncAttributeMaxDynamicSharedMemorySize, GEMM_SMEM);
    cudaFuncSetAttribute(gemm_mma_kernel<3>, cudaFuncAttributeMaxDynamicSharedMemorySize, GEMM_SMEM);
    cudaFuncSetAttribute(flash_kernel, cudaFuncAttributeMaxDynamicSharedMemorySize, FLASH_SMEM);

    // 1. weight transpose -> fp16
    wqkv_fp16_kernel<<<dim3(E_/32, NQKV/32), 256>>>(Wq, Wk, Wv, (__half*)wqkv);
    wt_fp16_kernel<<<dim3(E_/32, E_/32), 256>>>(Wo, E_, E_, (__half*)wo);
    wt_fp16_kernel<<<dim3(E_/32, FF_/32), 256>>>(W1, E_, FF_, (__half*)w1);
    wt_fp16_kernel<<<dim3(FF_/32, E_/32), 256>>>(W2, FF_, E_, (__half*)w2);
    // 2. LN1 -> fp16
    ln_fp16_kernel<<<TOK, 256>>>(x, g1, be1, (__half*)nx);
    // 3. fused QKV GEMM (N=3072) -> q,k fp16 [B,H,S,DH]; v fp16 [B,H,DH,S]
    gemm_mma_kernel<0><<<dim3(NQKV/128, TOK/128), 256, GEMM_SMEM>>>(
        (__half*)nx, (__half*)wqkv, nullptr, nullptr, nullptr, nullptr,
        (__half*)q, (__half*)k, (__half*)vt, E_, 0);
    // 4. HMMA flash attention -> attn fp16
    flash_kernel<<<dim3(S_/128, H_, B_), 256, FLASH_SMEM>>>(
        (__half*)q, (__half*)k, (__half*)vt, (__half*)attn);
    // 5. output projection + residual -> x1 fp32
    gemm_mma_kernel<1><<<dim3(E_/128, TOK/128), 256, GEMM_SMEM>>>(
        (__half*)attn, (__half*)wo, bo, x,
        (float*)x1, nullptr, nullptr, nullptr, nullptr, E_, E_);
    // 6. LN2 -> fp16
    ln_fp16_kernel<<<TOK, 256>>>((float*)x1, g2, be2, (__half*)nx2);
    // 7. FFN1: relu(+b1) -> ffn fp16
    gemm_mma_kernel<2><<<dim3(FF_/128, TOK/128), 256, GEMM_SMEM>>>(
        (__half*)nx2, (__half*)w1, b1, nullptr,
        nullptr, (__half*)ffn, nullptr, nullptr, nullptr, E_, FF_);
    // 8. FFN2: +b2 +x1 -> out
    gemm_mma_kernel<3><<<dim3(E_/128, TOK/128), 256, GEMM_SMEM>>>(
        (__half*)ffn, (__half*)w2, b2, (float*)x1,
        out, nullptr, nullptr, nullptr, nullptr, FF_, E_);
}

// round 10
// speedup vs baseline: 4.3674x; 1.1655x over previous
#include <cuda_runtime.h>
#include <cuda_fp16.h>
#include <cstdint>

#define B_   2
#define S_   2048
#define E_   1024
#define H_   16
#define DH_  64
#define FF_  4096
#define TOK  (B_*S_)   // 4096
#define NQKV 3072

// ---------------- scratch (no allocs allowed) ----------------
__device__ __half g_nx   [TOK*(size_t)E_];
__device__ __half g_wqkv [(size_t)NQKV*E_];
__device__ __half g_wo   [(size_t)E_*E_];
__device__ __half g_w1   [(size_t)FF_*E_];
__device__ __half g_w2   [(size_t)E_*FF_];
__device__ __half g_q [(size_t)B_*H_*S_*DH_];
__device__ __half g_k [(size_t)B_*H_*S_*DH_];
__device__ __half g_vt[(size_t)B_*H_*DH_*S_];   // V transposed: [B,H,DH,S]
__device__ __half g_attn[TOK*(size_t)E_];
__device__ float g_x1[TOK*(size_t)E_];
__device__ __half g_nx2 [TOK*(size_t)E_];
__device__ __half g_ffn [TOK*(size_t)FF_];

// ---------------- PTX helpers (base-target-safe: sm_80 features) -------------
__device__ __forceinline__ uint32_t smem_u32(const void* p) {
    uint32_t a;
    asm("{ .reg .u64 t; cvta.to.shared.u64 t, %1; cvt.u32.u64 %0, t; }" : "=r"(a) : "l"(p));
    return a;
}
__device__ __forceinline__ uint32_t h2_as_u32(__half2 h) {
    union { __half2 h2; uint32_t u; } cvt;
    cvt.h2 = h;
    return cvt.u;
}
__device__ __forceinline__ void cp16(uint32_t s, const void* g) {
    asm volatile("cp.async.cg.shared.global [%0], [%1], 16;" :: "r"(s), "l"(g));
}
#define CP_COMMIT() asm volatile("cp.async.commit_group;" ::: "memory")
#define CP_WAIT(n)  asm volatile("cp.async.wait_group %0;" :: "n"(n) : "memory")

__device__ __forceinline__ void ldm_x4(uint32_t& r0, uint32_t& r1, uint32_t& r2,
                                       uint32_t& r3, uint32_t a) {
    asm volatile("ldmatrix.sync.aligned.m8n8.x4.shared.b16 {%0,%1,%2,%3}, [%4];"
                 : "=r"(r0), "=r"(r1), "=r"(r2), "=r"(r3) : "r"(a));
}
__device__ __forceinline__ void mma16816(float* c, uint32_t a0, uint32_t a1,
                                         uint32_t a2, uint32_t a3,
                                         uint32_t b0, uint32_t b1) {
    asm volatile(
        "mma.sync.aligned.m16n8k16.row.col.f32.f16.f16.f32 "
        "{%0,%1,%2,%3},{%4,%5,%6,%7},{%8,%9},{%0,%1,%2,%3};"
        : "+f"(c[0]), "+f"(c[1]), "+f"(c[2]), "+f"(c[3])
        : "r"(a0), "r"(a1), "r"(a2), "r"(a3), "r"(b0), "r"(b1));
}

// fast 2^x on the FMA pipe (no MUFU). x clamped to [-125, ~0]. rel err ~1e-7.
__device__ __forceinline__ float fexp2(float x) {
    x = fmaxf(x, -125.0f);
    float t = x + 12582912.0f;              // 1.5*2^23: round-to-int in mantissa
    int n = __float_as_int(t) - 0x4B400000; // integer part
    float f = x - (t - 12582912.0f);        // frac in [-0.5, 0.5]
    float p =              1.5403530e-4f;
    p = fmaf(p, f, 1.3333558e-3f);
    p = fmaf(p, f, 9.6181291e-3f);
    p = fmaf(p, f, 5.5504109e-2f);
    p = fmaf(p, f, 2.4022651e-1f);
    p = fmaf(p, f, 6.9314718e-1f);
    p = fmaf(p, f, 1.0f);
    return p * __int_as_float((n + 127) << 23);
}

// ---------------- LayerNorm -> fp16: one block per token ---------------------
__global__ void __launch_bounds__(256) ln_fp16_kernel(
    const float* __restrict__ x, const float* __restrict__ g,
    const float* __restrict__ bta, __half* __restrict__ o)
{
    __shared__ float sh1[8], sh2[8];
    int tok = blockIdx.x;
    int t = threadIdx.x;
    const float4* xr = (const float4*)(x + (size_t)tok * E_);
    float4 v = xr[t];
    float sum = v.x + v.y + v.z + v.w;
    float sq  = v.x*v.x + v.y*v.y + v.z*v.z + v.w*v.w;
    #pragma unroll
    for (int o2 = 16; o2 > 0; o2 >>= 1) {
        sum += __shfl_xor_sync(0xffffffffu, sum, o2);
        sq  += __shfl_xor_sync(0xffffffffu, sq,  o2);
    }
    if ((t & 31) == 0) { sh1[t >> 5] = sum; sh2[t >> 5] = sq; }
    __syncthreads();
    if (t < 32) {
        sum = (t < 8) ? sh1[t] : 0.f;
        sq  = (t < 8) ? sh2[t] : 0.f;
        #pragma unroll
        for (int o2 = 4; o2 > 0; o2 >>= 1) {
            sum += __shfl_xor_sync(0xffffffffu, sum, o2);
            sq  += __shfl_xor_sync(0xffffffffu, sq,  o2);
        }
        if (t == 0) { sh1[0] = sum; sh2[0] = sq; }
    }
    __syncthreads();
    sum = sh1[0]; sq = sh2[0];
    float mu  = sum * (1.0f / E_);
    float var = sq * (1.0f / E_) - mu * mu;
    float rs  = rsqrtf(var + 1e-5f);
    float4 gv = ((const float4*)g)[t];
    float4 bv = ((const float4*)bta)[t];
    float a0 = (v.x - mu) * rs * gv.x + bv.x;
    float a1 = (v.y - mu) * rs * gv.y + bv.y;
    float a2 = (v.z - mu) * rs * gv.z + bv.z;
    float a3 = (v.w - mu) * rs * gv.w + bv.w;
    size_t base = (size_t)tok * E_ + t * 4;
    *(__half2*)(o + base)     = __floats2half2_rn(a0, a1);
    *(__half2*)(o + base + 2) = __floats2half2_rn(a2, a3);
}

// ---------------- weight transpose -> fp16: W[K,N] -> Wt[N,K] ----------------
__global__ void __launch_bounds__(256) wt_fp16_kernel(
    const float* __restrict__ W, int K, int N, __half* __restrict__ o)
{
    __shared__ float t[32][33];
    int k0 = blockIdx.x * 32, n0 = blockIdx.y * 32;
    int tx = threadIdx.x & 31, ty = threadIdx.x >> 5;
    #pragma unroll
    for (int r = 0; r < 4; r++)
        t[ty + 8*r][tx] = W[(size_t)(k0 + ty + 8*r) * N + n0 + tx];
    __syncthreads();
    #pragma unroll
    for (int r = 0; r < 4; r++)
        o[(size_t)(n0 + ty + 8*r) * K + k0 + tx] = __float2half_rn(t[tx][ty + 8*r]);
}

// QKV weights [H,E,DH] x3 -> fused Wt[3072, E] fp16
__global__ void __launch_bounds__(256) wqkv_fp16_kernel(
    const float* __restrict__ Wq, const float* __restrict__ Wk,
    const float* __restrict__ Wv, __half* __restrict__ o)
{
    __shared__ float t[32][33];
    int e0 = blockIdx.x * 32, n0 = blockIdx.y * 32;
    const float* Wm = (n0 < 1024) ? Wq : (n0 < 2048) ? Wk : Wv;
    int nn = n0 & 1023;
    int h = nn >> 6, d0 = nn & 63;
    int tx = threadIdx.x & 31, ty = threadIdx.x >> 5;
    #pragma unroll
    for (int r = 0; r < 4; r++)
        t[ty + 8*r][tx] = Wm[((size_t)h * E_ + e0 + ty + 8*r) * DH_ + d0 + tx];
    __syncthreads();
    #pragma unroll
    for (int r = 0; r < 4; r++)
        o[(size_t)(n0 + ty + 8*r) * E_ + e0 + tx] = __float2half_rn(t[tx][ty + 8*r]);
}

// ---------------- HMMA GEMM: C[M,N] = A[M,K]*Bt[N,K]^T, plain fp16 -----------
// 128 threads, 4 warps, each warp 64x64 (2x2 warp grid on 128x128 CTA tile)
// MODE 0: QKV scatter: q,k fp16 [B,H,S,DH]; v fp16 transposed [B,H,DH,S]
// MODE 1/3: + bias + res -> o0 fp32
// MODE 2: relu(+bias) -> oh fp16
#define BK     32
#define LDS    40
#define AELEMS (128 * LDS)
#define ABYTES (AELEMS * 2)            // 10240
#define STG_BYTES (2 * ABYTES)
#define GEMM_SMEM (4 * STG_BYTES)      // 81920 -> 2 CTA/SM

template<int MODE>
__global__ void __launch_bounds__(128, 2) gemm_mma_kernel(
    const __half* __restrict__ A, const __half* __restrict__ Bt,
    const float* __restrict__ bias, const float* __restrict__ res,
    float* __restrict__ o0, __half* __restrict__ oh,
    __half* __restrict__ q16, __half* __restrict__ k16, __half* __restrict__ v16,
    int K, int ldC)
{
    extern __shared__ __half smbuf[];
    const uint32_t sbase = smem_u32(smbuf);
    const int NIT = K / BK;
    const int t = threadIdx.x;
    const int wid = t >> 5, lane = t & 31;
    const int bm = blockIdx.y * 128, bn = blockIdx.x * 128;
    const int wm = (wid & 1) * 64, wn = (wid >> 1) * 64;

    const __half* Abase = A  + (size_t)bm * K;
    const __half* Bbase = Bt + (size_t)bn * K;

    auto load_stage = [&](int st, int i) {
        uint32_t sa = sbase + st * STG_BYTES;
        int kc = i * BK;
        #pragma unroll
        for (int p = 0; p < 4; p++) {
            int idx = t + p * 128;
            int row = idx >> 2, ch = idx & 3;
            uint32_t off = (uint32_t)(row * LDS + ch * 8) * 2;
            cp16(sa + off,          Abase + (size_t)row * K + kc + ch * 8);
            cp16(sa + ABYTES + off, Bbase + (size_t)row * K + kc + ch * 8);
        }
    };

    #pragma unroll
    for (int s = 0; s < 3; s++) { load_stage(s, s); CP_COMMIT(); }

    float c[4][8][4];
    #pragma unroll
    for (int mt = 0; mt < 4; mt++)
        #pragma unroll
        for (int nt = 0; nt < 8; nt++)
            #pragma unroll
            for (int e = 0; e < 4; e++) c[mt][nt][e] = 0.f;

    for (int i = 0; i < NIT; i++) {
        CP_WAIT(2);
        __syncthreads();
        if (i + 3 < NIT) load_stage((i + 3) & 3, i + 3);
        CP_COMMIT();

        uint32_t sa = sbase + (i & 3) * STG_BYTES;
        uint32_t sb = sa + ABYTES;
        #pragma unroll
        for (int ks = 0; ks < 2; ks++) {
            uint32_t a[4][4];
            #pragma unroll
            for (int mt = 0; mt < 4; mt++) {
                uint32_t addr = sa + (uint32_t)(((wm + mt*16 + (lane & 15)) * LDS
                                  + ks*16 + (lane >> 4) * 8) * 2);
                ldm_x4(a[mt][0], a[mt][1], a[mt][2], a[mt][3], addr);
            }
            uint32_t b[8][2];
            #pragma unroll
            for (int np = 0; np < 4; np++) {
                int nrow = wn + np*16 + (lane & 7) + ((lane >> 4) << 3);
                int ncol = ks*16 + (((lane >> 3) & 1) << 3);
                uint32_t addr = sb + (uint32_t)((nrow * LDS + ncol) * 2);
                uint32_t r0, r1, r2, r3;
                ldm_x4(r0, r1, r2, r3, addr);
                b[2*np][0] = r0; b[2*np][1] = r1;
                b[2*np+1][0] = r2; b[2*np+1][1] = r3;
            }
            #pragma unroll
            for (int mt = 0; mt < 4; mt++)
                #pragma unroll
                for (int nt = 0; nt < 8; nt++)
                    mma16816(c[mt][nt], a[mt][0], a[mt][1], a[mt][2], a[mt][3],
                             b[nt][0], b[nt][1]);
        }
    }

    // ---------------- epilogue ----------------
    const int r = lane >> 2, cq = (lane & 3) * 2;
    #pragma unroll
    for (int mt = 0; mt < 4; mt++) {
        #pragma unroll
        for (int half_ = 0; half_ < 2; half_++) {
            int m = bm + wm + mt * 16 + r + half_ * 8;
            #pragma unroll
            for (int nt = 0; nt < 8; nt++) {
                int n = bn + wn + nt * 8 + cq;
                float v0 = c[mt][nt][half_ * 2 + 0];
                float v1 = c[mt][nt][half_ * 2 + 1];
                if (MODE == 0) {
                    int mat = n >> 10;
                    int hh = (n & 1023) >> 6, d = n & 63;
                    int bb = m >> 11, srow = m & (S_ - 1);
                    if (mat < 2) {
                        __half* dst = (mat == 0) ? q16 : k16;
                        *(__half2*)(dst + (((size_t)(bb * H_ + hh) * S_ + srow) << 6) + d)
                            = __floats2half2_rn(v0, v1);
                    } else {
                        __half* p = v16 + ((size_t)(bb * H_ + hh) * DH_ + d) * S_ + srow;
                        p[0]  = __float2half_rn(v0);
                        p[S_] = __float2half_rn(v1);
                    }
                } else if (MODE == 2) {
                    float2 bv = *(const float2*)(bias + n);
                    v0 = fmaxf(v0 + bv.x, 0.f);
                    v1 = fmaxf(v1 + bv.y, 0.f);
                    *(__half2*)(oh + (size_t)m * ldC + n) = __floats2half2_rn(v0, v1);
                } else {
                    size_t base = (size_t)m * ldC + n;
                    float2 bv = *(const float2*)(bias + n);
                    float2 rv = *(const float2*)(res + base);
                    *(float2*)(o0 + base) = make_float2(v0 + bv.x + rv.x,
                                                        v1 + bv.y + rv.y);
                }
            }
        }
    }
}

// ---------------- HMMA flash attention (causal) -------------------------------
// 128 queries x 64 keys per tile, 4 warps (32 q-rows each), fp16 in, fp16 out.
// Q,K: [B,H,S,DH] fp16; Vt: [B,H,DH,S] fp16; O: [B,S,E] fp16 (concat layout)
#define FLDS 72
#define FLASH_SMEM ((128 + 4*64) * FLDS * 2)   // 55296 B

__global__ void __launch_bounds__(128, 2) flash_kernel(
    const __half* __restrict__ Q, const __half* __restrict__ Kp,
    const __half* __restrict__ Vt, __half* __restrict__ O)
{
    extern __shared__ __half fsm[];
    const uint32_t qb = smem_u32(fsm);                 // Q [128][72]
    const uint32_t kb = qb + 128 * FLDS * 2;           // K [2][64][72]
    const uint32_t vb = kb + 2 * 64 * FLDS * 2;        // Vt [2][64][72]

    const int qt = (int)gridDim.x - 1 - (int)blockIdx.x;   // heavy tiles first
    const int h = blockIdx.y, b = blockIdx.z;
    const int t = threadIdx.x, wid = t >> 5, lane = t & 31;
    const int wm = wid * 32;

    const __half* Qg = Q  + (((size_t)(b * H_ + h)) * S_ + qt * 128) * DH_;
    const __half* Kg = Kp + ((size_t)(b * H_ + h)) * S_ * DH_;
    const __half* Vg = Vt + ((size_t)(b * H_ + h)) * DH_ * S_;

    auto load_kv = [&](int kt) {
        uint32_t st = (uint32_t)(kt & 1) * 64 * FLDS * 2;
        #pragma unroll
        for (int p = 0; p < 4; p++) {
            int idx = t + p * 128;
            int row = idx >> 3, ch = idx & 7;
            uint32_t off = (uint32_t)(row * FLDS + ch * 8) * 2;
            cp16(kb + st + off, Kg + (size_t)(kt * 64 + row) * DH_ + ch * 8);
            cp16(vb + st + off, Vg + (size_t)row * S_ + kt * 64 + ch * 8);
        }
    };

    // Q + KV(0) in one group
    #pragma unroll
    for (int p = 0; p < 8; p++) {
        int idx = t + p * 128;
        int row = idx >> 3, ch = idx & 7;
        cp16(qb + (uint32_t)(row * FLDS + ch * 8) * 2, Qg + (size_t)row * DH_ + ch * 8);
    }
    load_kv(0);
    CP_COMMIT();

    const float alpha = 0.125f * 1.44269504f;   // scale * log2(e)
    float mrow[2][2], lrow[2][2];
    #pragma unroll
    for (int mt = 0; mt < 2; mt++) {
        mrow[mt][0] = -1e30f; mrow[mt][1] = -1e30f;
        lrow[mt][0] = 0.f;    lrow[mt][1] = 0.f;
    }
    float oc[2][8][4];
    #pragma unroll
    for (int mt = 0; mt < 2; mt++)
        #pragma unroll
        for (int j = 0; j < 8; j++)
            #pragma unroll
            for (int e = 0; e < 4; e++) oc[mt][j][e] = 0.f;

    uint32_t qa[2][4][4];
    const int nkt = 2 * qt + 2;

    for (int kt = 0; kt < nkt; kt++) {
        if (kt + 1 < nkt) { load_kv(kt + 1); CP_COMMIT(); CP_WAIT(1); }
        else              { CP_WAIT(0); }
        __syncthreads();

        if (kt == 0) {   // Q fragments, loaded once
            #pragma unroll
            for (int mt = 0; mt < 2; mt++)
                #pragma unroll
                for (int ks = 0; ks < 4; ks++) {
                    uint32_t addr = qb + (uint32_t)(((wm + mt*16 + (lane & 15)) * FLDS
                                       + ks * 16 + (lane >> 4) * 8) * 2);
                    ldm_x4(qa[mt][ks][0], qa[mt][ks][1], qa[mt][ks][2], qa[mt][ks][3], addr);
                }
        }

        // ---- S = Q K^T ----
        float sc[2][8][4];
        #pragma unroll
        for (int mt = 0; mt < 2; mt++)
            #pragma unroll
            for (int j = 0; j < 8; j++)
                #pragma unroll
                for (int e = 0; e < 4; e++) sc[mt][j][e] = 0.f;

        uint32_t kbs = kb + (uint32_t)(kt & 1) * 64 * FLDS * 2;
        #pragma unroll
        for (int ks = 0; ks < 4; ks++) {
            uint32_t bfr[8][2];
            #pragma unroll
            for (int np = 0; np < 4; np++) {
                int nrow = np * 16 + (lane & 7) + ((lane >> 4) << 3);
                int ncol = ks * 16 + (((lane >> 3) & 1) << 3);
                uint32_t r0, r1, r2, r3;
                ldm_x4(r0, r1, r2, r3, kbs + (uint32_t)((nrow * FLDS + ncol) * 2));
                bfr[2*np][0] = r0; bfr[2*np][1] = r1;
                bfr[2*np+1][0] = r2; bfr[2*np+1][1] = r3;
            }
            #pragma unroll
            for (int mt = 0; mt < 2; mt++)
                #pragma unroll
                for (int j = 0; j < 8; j++)
                    mma16816(sc[mt][j], qa[mt][ks][0], qa[mt][ks][1],
                             qa[mt][ks][2], qa[mt][ks][3], bfr[j][0], bfr[j][1]);
        }

        // ---- causal mask (only diagonal key tiles) ----
        if (kt >= 2 * qt) {
            #pragma unroll
            for (int mt = 0; mt < 2; mt++) {
                int row0 = qt * 128 + wm + mt * 16 + (lane >> 2);
                int colb = kt * 64 + 2 * (lane & 3);
                #pragma unroll
                for (int j = 0; j < 8; j++) {
                    #pragma unroll
                    for (int cc = 0; cc < 2; cc++) {
                        int col = colb + j * 8 + cc;
                        if (col > row0)     sc[mt][j][cc]     = -1e30f;
                        if (col > row0 + 8) sc[mt][j][2 + cc] = -1e30f;
                    }
                }
            }
        }

        // ---- online softmax + P packing ----
        uint32_t pa[2][4][4];
        float corr[2][2];
        #pragma unroll
        for (int mt = 0; mt < 2; mt++) {
            float mx0 = -1e30f, mx1 = -1e30f;
            #pragma unroll
            for (int j = 0; j < 8; j++) {
                mx0 = fmaxf(mx0, fmaxf(sc[mt][j][0], sc[mt][j][1]));
                mx1 = fmaxf(mx1, fmaxf(sc[mt][j][2], sc[mt][j][3]));
            }
            mx0 = fmaxf(mx0, __shfl_xor_sync(0xffffffffu, mx0, 1));
            mx0 = fmaxf(mx0, __shfl_xor_sync(0xffffffffu, mx0, 2));
            mx1 = fmaxf(mx1, __shfl_xor_sync(0xffffffffu, mx1, 1));
            mx1 = fmaxf(mx1, __shfl_xor_sync(0xffffffffu, mx1, 2));
            float nm0 = fmaxf(mrow[mt][0], mx0), nm1 = fmaxf(mrow[mt][1], mx1);
            corr[mt][0] = fexp2((mrow[mt][0] - nm0) * alpha);
            corr[mt][1] = fexp2((mrow[mt][1] - nm1) * alpha);
            mrow[mt][0] = nm0; mrow[mt][1] = nm1;
            float ma0 = nm0 * alpha, ma1 = nm1 * alpha;

            float rs0 = 0.f, rs1 = 0.f;
            #pragma unroll
            for (int j = 0; j < 8; j++) {
                float p0 = fexp2(fmaf(sc[mt][j][0], alpha, -ma0));
                float p1 = fexp2(fmaf(sc[mt][j][1], alpha, -ma0));
                float p2 = fexp2(fmaf(sc[mt][j][2], alpha, -ma1));
                float p3 = fexp2(fmaf(sc[mt][j][3], alpha, -ma1));
                rs0 += p0 + p1; rs1 += p2 + p3;
                int ks = j >> 1, hi = (j & 1) << 1;
                pa[mt][ks][hi]     = h2_as_u32(__floats2half2_rn(p0, p1));
                pa[mt][ks][hi + 1] = h2_as_u32(__floats2half2_rn(p2, p3));
            }
            rs0 += __shfl_xor_sync(0xffffffffu, rs0, 1);
            rs0 += __shfl_xor_sync(0xffffffffu, rs0, 2);
            rs1 += __shfl_xor_sync(0xffffffffu, rs1, 1);
            rs1 += __shfl_xor_sync(0xffffffffu, rs1, 2);
            lrow[mt][0] = lrow[mt][0] * corr[mt][0] + rs0;
            lrow[mt][1] = lrow[mt][1] * corr[mt][1] + rs1;
            #pragma unroll
            for (int j = 0; j < 8; j++) {
                oc[mt][j][0] *= corr[mt][0]; oc[mt][j][1] *= corr[mt][0];
                oc[mt][j][2] *= corr[mt][1]; oc[mt][j][3] *= corr[mt][1];
            }
        }

        // ---- O += P V ----
        uint32_t vbs = vb + (uint32_t)(kt & 1) * 64 * FLDS * 2;
        #pragma unroll
        for (int ks = 0; ks < 4; ks++) {
            uint32_t vfr[8][2];
            #pragma unroll
            for (int np = 0; np < 4; np++) {
                int nrow = np * 16 + (lane & 7) + ((lane >> 4) << 3);
                int ncol = ks * 16 + (((lane >> 3) & 1) << 3);
                uint32_t r0, r1, r2, r3;
                ldm_x4(r0, r1, r2, r3, vbs + (uint32_t)((nrow * FLDS + ncol) * 2));
                vfr[2*np][0] = r0; vfr[2*np][1] = r1;
                vfr[2*np+1][0] = r2; vfr[2*np+1][1] = r3;
            }
            #pragma unroll
            for (int mt = 0; mt < 2; mt++)
                #pragma unroll
                for (int j = 0; j < 8; j++)
                    mma16816(oc[mt][j], pa[mt][ks][0], pa[mt][ks][1],
                             pa[mt][ks][2], pa[mt][ks][3], vfr[j][0], vfr[j][1]);
        }
        __syncthreads();
    }

    // ---- write O (concat layout, fp16) ----
    #pragma unroll
    for (int mt = 0; mt < 2; mt++) {
        float i0 = 1.0f / lrow[mt][0], i1 = 1.0f / lrow[mt][1];
        int row0 = qt * 128 + wm + mt * 16 + (lane >> 2);
        size_t base0 = ((size_t)b * S_ + row0) * E_ + h * 64 + 2 * (lane & 3);
        size_t base1 = base0 + (size_t)8 * E_;
        #pragma unroll
        for (int j = 0; j < 8; j++) {
            *(__half2*)(O + base0 + j * 8) = __floats2half2_rn(oc[mt][j][0] * i0,
                                                               oc[mt][j][1] * i0);
            *(__half2*)(O + base1 + j * 8) = __floats2half2_rn(oc[mt][j][2] * i1,
                                                               oc[mt][j][3] * i1);
        }
    }
}

// ---------------- host launcher ----------------
extern "C" void kernel_launch(void* const* d_in, const int* in_sizes, int n_in,
                              void* d_out, int out_size)
{
    const float* x   = (const float*)d_in[0];
    const float* Wq  = (const float*)d_in[1];
    const float* Wk  = (const float*)d_in[2];
    const float* Wv  = (const float*)d_in[3];
    const float* Wo  = (const float*)d_in[4];
    const float* bo  = (const float*)d_in[5];
    const float* W1  = (const float*)d_in[6];
    const float* b1  = (const float*)d_in[7];
    const float* W2  = (const float*)d_in[8];
    const float* b2  = (const float*)d_in[9];
    const float* g1  = (const float*)d_in[10];
    const float* be1 = (const float*)d_in[11];
    const float* g2  = (const float*)d_in[12];
    const float* be2 = (const float*)d_in[13];
    float* out = (float*)d_out;

    void *nx, *wqkv, *wo, *w1, *w2, *q, *k, *vt, *attn, *x1, *nx2, *ffn;
    cudaGetSymbolAddress(&nx, g_nx);
    cudaGetSymbolAddress(&wqkv, g_wqkv);
    cudaGetSymbolAddress(&wo, g_wo);
    cudaGetSymbolAddress(&w1, g_w1);
    cudaGetSymbolAddress(&w2, g_w2);
    cudaGetSymbolAddress(&q, g_q); cudaGetSymbolAddress(&k, g_k);
    cudaGetSymbolAddress(&vt, g_vt);
    cudaGetSymbolAddress(&attn, g_attn);
    cudaGetSymbolAddress(&x1, g_x1);
    cudaGetSymbolAddress(&nx2, g_nx2);
    cudaGetSymbolAddress(&ffn, g_ffn);

    cudaFuncSetAttribute(gemm_mma_kernel<0>, cudaFuncAttributeMaxDynamicSharedMemorySize, GEMM_SMEM);
    cudaFuncSetAttribute(gemm_mma_kernel<1>, cudaFuncAttributeMaxDynamicSharedMemorySize, GEMM_SMEM);
    cudaFuncSetAttribute(gemm_mma_kernel<2>, cudaFuncAttributeMaxDynamicSharedMemorySize, GEMM_SMEM);
    cudaFuncSetAttribute(gemm_mma_kernel<3>, cudaFuncAttributeMaxDynamicSharedMemorySize, GEMM_SMEM);
    cudaFuncSetAttribute(flash_kernel, cudaFuncAttributeMaxDynamicSharedMemorySize, FLASH_SMEM);

    // 1. weight transpose -> fp16
    wqkv_fp16_kernel<<<dim3(E_/32, NQKV/32), 256>>>(Wq, Wk, Wv, (__half*)wqkv);
    wt_fp16_kernel<<<dim3(E_/32, E_/32), 256>>>(Wo, E_, E_, (__half*)wo);
    wt_fp16_kernel<<<dim3(E_/32, FF_/32), 256>>>(W1, E_, FF_, (__half*)w1);
    wt_fp16_kernel<<<dim3(FF_/32, E_/32), 256>>>(W2, FF_, E_, (__half*)w2);
    // 2. LN1 -> fp16
    ln_fp16_kernel<<<TOK, 256>>>(x, g1, be1, (__half*)nx);
    // 3. fused QKV GEMM (N=3072) -> q,k fp16 [B,H,S,DH]; v fp16 [B,H,DH,S]
    gemm_mma_kernel<0><<<dim3(NQKV/128, TOK/128), 128, GEMM_SMEM>>>(
        (__half*)nx, (__half*)wqkv, nullptr, nullptr, nullptr, nullptr,
        (__half*)q, (__half*)k, (__half*)vt, E_, 0);
    // 4. HMMA flash attention -> attn fp16
    flash_kernel<<<dim3(S_/128, H_, B_), 128, FLASH_SMEM>>>(
        (__half*)q, (__half*)k, (__half*)vt, (__half*)attn);
    // 5. output projection + residual -> x1 fp32
    gemm_mma_kernel<1><<<dim3(E_/128, TOK/128), 128, GEMM_SMEM>>>(
        (__half*)attn, (__half*)wo, bo, x,
        (float*)x1, nullptr, nullptr, nullptr, nullptr, E_, E_);
    // 6. LN2 -> fp16
    ln_fp16_kernel<<<TOK, 256>>>((float*)x1, g2, be2, (__half*)nx2);
    // 7. FFN1: relu(+b1) -> ffn fp16
    gemm_mma_kernel<2><<<dim3(FF_/128, TOK/128), 128, GEMM_SMEM>>>(
        (__half*)nx2, (__half*)w1, b1, nullptr,
        nullptr, (__half*)ffn, nullptr, nullptr, nullptr, E_, FF_);
    // 8. FFN2: +b2 +x1 -> out
    gemm_mma_kernel<3><<<dim3(E_/128, TOK/128), 128, GEMM_SMEM>>>(
        (__half*)ffn, (__half*)w2, b2, (float*)x1,
        out, nullptr, nullptr, nullptr, nullptr, FF_, E_);
}